// round 2
// baseline (speedup 1.0000x reference)
#include <cuda_runtime.h>
#include <math.h>

// Problem constants
#define Bsz   4
#define Tsz   2048
#define DM    1024
#define Hn    16
#define HDsz  64
#define NFsz  128
#define CH    64              // chunk size for chunked causal linear attention
#define NCH   (Tsz / CH)      // 32 chunks
#define BHn   (Bsz * Hn)      // 64 (b,h) sequences
#define EPSv  1e-6f
#define INV_SQRT_NF 0.08838834764831845f  // 1/sqrt(128)

#define M_ROWS (Bsz * Tsz)    // 8192

// -------------------- scratch (device globals; no allocation allowed) ------
__device__ float g_q [BHn * Tsz * HDsz];   // (b,h,t,d)
__device__ float g_k [BHn * Tsz * HDsz];
__device__ float g_v [BHn * Tsz * HDsz];
__device__ float g_qp[BHn * Tsz * NFsz];   // (b,h,t,f)
__device__ float g_kp[BHn * Tsz * NFsz];
__device__ float g_S [BHn * NCH * NFsz * HDsz];  // per-chunk K^T V sums -> excl prefix
__device__ float g_z [BHn * NCH * NFsz];         // per-chunk k sums    -> excl prefix
__device__ float g_y [Bsz * Tsz * Hn * HDsz];    // (b,t,h,e) flat rows of 1024

// ---------------------------------------------------------------------------
// SGEMM: C = A(MxK) * B(KxN), row-major. BM=BN=128, BK=8, 8x8 per thread.
// HEAD_OUT=true writes C in (b,h,t,d) head-major layout for q/k/v.
// ---------------------------------------------------------------------------
template <bool HEAD_OUT>
__global__ __launch_bounds__(256) void sgemm_kernel(
    const float* __restrict__ A, const float* __restrict__ B,
    float* __restrict__ C, int M, int N, int K)
{
    const int BM = 128, BN = 128, BK = 8, TM = 8, TN = 8;
    __shared__ float As[BK * BM];   // transposed: As[k][m]
    __shared__ float Bs[BK * BN];   // Bs[k][n]

    const int tid  = threadIdx.x;
    const int bRow = blockIdx.y, bCol = blockIdx.x;

    const float* Ag = A + (size_t)bRow * BM * K;
    const float* Bg = B + (size_t)bCol * BN;

    const int innerRowA = tid >> 1;            // 0..127
    const int innerColA = (tid & 1) * 4;       // 0 or 4
    const int innerRowB = tid >> 5;            // 0..7
    const int innerColB = (tid & 31) * 4;      // 0..124
    const int threadRow = tid >> 4;            // 0..15
    const int threadCol = tid & 15;            // 0..15

    float acc[TM][TN] = {};
    float regM[TM], regN[TN];

    for (int bk = 0; bk < K; bk += BK) {
        float4 a4 = *reinterpret_cast<const float4*>(Ag + (size_t)innerRowA * K + bk + innerColA);
        As[(innerColA + 0) * BM + innerRowA] = a4.x;
        As[(innerColA + 1) * BM + innerRowA] = a4.y;
        As[(innerColA + 2) * BM + innerRowA] = a4.z;
        As[(innerColA + 3) * BM + innerRowA] = a4.w;
        *reinterpret_cast<float4*>(Bs + innerRowB * BN + innerColB) =
            *reinterpret_cast<const float4*>(Bg + (size_t)(bk + innerRowB) * N + innerColB);
        __syncthreads();

        #pragma unroll
        for (int k = 0; k < BK; k++) {
            #pragma unroll
            for (int i = 0; i < TM; i++) regM[i] = As[k * BM + threadRow * TM + i];
            #pragma unroll
            for (int j = 0; j < TN; j++) regN[j] = Bs[k * BN + threadCol * TN + j];
            #pragma unroll
            for (int i = 0; i < TM; i++)
                #pragma unroll
                for (int j = 0; j < TN; j++)
                    acc[i][j] += regM[i] * regN[j];
        }
        __syncthreads();
    }

    #pragma unroll
    for (int i = 0; i < TM; i++) {
        const int m = bRow * BM + threadRow * TM + i;
        #pragma unroll
        for (int j = 0; j < TN; j++) {
            const int n = bCol * BN + threadCol * TN + j;
            if (HEAD_OUT) {
                const int b = m / Tsz, t = m % Tsz;
                const int h = n >> 6, d = n & 63;
                C[(((size_t)(b * Hn + h)) * Tsz + t) * HDsz + d] = acc[i][j];
            } else {
                C[(size_t)m * N + n] = acc[i][j];
            }
        }
    }
}

// ---------------------------------------------------------------------------
// Feature map: phi(x) = exp(x @ Wf - 0.5*||x||^2) * INV_SQRT_NF
// rows = BH*T (row-major over (bh,t)); each warp handles 8 rows.
// ---------------------------------------------------------------------------
__global__ __launch_bounds__(256) void featmap_kernel(
    const float* __restrict__ in, const float* __restrict__ Wf,
    float* __restrict__ out)
{
    __shared__ float Ws[HDsz * NFsz];   // 32 KB, [d][j]
    const int tid = threadIdx.x;
    for (int i = tid; i < HDsz * NFsz; i += 256) Ws[i] = Wf[i];
    __syncthreads();

    const int warp = tid >> 5, lane = tid & 31;
    const int row0 = blockIdx.x * 64 + warp * 8;

    for (int rr = 0; rr < 8; rr++) {
        const int r = row0 + rr;
        const float* q = in + (size_t)r * HDsz;
        const float q0 = q[lane], q1 = q[lane + 32];
        float v = q0 * q0 + q1 * q1;
        #pragma unroll
        for (int o = 16; o > 0; o >>= 1) v += __shfl_xor_sync(0xffffffffu, v, o);
        const float sq = 0.5f * v;

        float acc[4] = {0.f, 0.f, 0.f, 0.f};
        #pragma unroll
        for (int d = 0; d < 32; d++) {
            const float qd = __shfl_sync(0xffffffffu, q0, d);
            #pragma unroll
            for (int jj = 0; jj < 4; jj++) acc[jj] += qd * Ws[d * NFsz + lane + 32 * jj];
        }
        #pragma unroll
        for (int d = 0; d < 32; d++) {
            const float qd = __shfl_sync(0xffffffffu, q1, d);
            #pragma unroll
            for (int jj = 0; jj < 4; jj++) acc[jj] += qd * Ws[(d + 32) * NFsz + lane + 32 * jj];
        }
        #pragma unroll
        for (int jj = 0; jj < 4; jj++)
            out[(size_t)r * NFsz + lane + 32 * jj] = expf(acc[jj] - sq) * INV_SQRT_NF;
    }
}

// ---------------------------------------------------------------------------
// Pass 1: per-chunk state sums  S_c = kp_c^T @ v_c  (NFxHD), z_c = sum kp_c
// grid: (NCH, BHn), 256 threads.
// ---------------------------------------------------------------------------
__global__ __launch_bounds__(256) void chunk_sums_kernel()
{
    __shared__ float kp_s[CH * NFsz];  // 32 KB
    __shared__ float v_s [CH * HDsz];  // 16 KB
    const int c = blockIdx.x, bh = blockIdx.y;
    const int tid = threadIdx.x;

    const float* kp = g_kp + (size_t)(bh * Tsz + c * CH) * NFsz;
    const float* vv = g_v  + (size_t)(bh * Tsz + c * CH) * HDsz;
    for (int i = tid; i < CH * NFsz; i += 256) kp_s[i] = kp[i];
    for (int i = tid; i < CH * HDsz; i += 256) v_s[i]  = vv[i];
    __syncthreads();

    const int d0 = (tid >> 3) * 4;   // 32 d-groups of 4
    const int e0 = (tid & 7) * 8;    // 8 e-groups of 8
    float acc[4][8] = {};
    for (int i = 0; i < CH; i++) {
        float kk[4], vr[8];
        #pragma unroll
        for (int dd = 0; dd < 4; dd++) kk[dd] = kp_s[i * NFsz + d0 + dd];
        #pragma unroll
        for (int ee = 0; ee < 8; ee++) vr[ee] = v_s[i * HDsz + e0 + ee];
        #pragma unroll
        for (int dd = 0; dd < 4; dd++)
            #pragma unroll
            for (int ee = 0; ee < 8; ee++) acc[dd][ee] += kk[dd] * vr[ee];
    }
    float* Sout = g_S + (size_t)(bh * NCH + c) * NFsz * HDsz;
    #pragma unroll
    for (int dd = 0; dd < 4; dd++)
        #pragma unroll
        for (int ee = 0; ee < 8; ee++)
            Sout[(d0 + dd) * HDsz + e0 + ee] = acc[dd][ee];

    if (tid < NFsz) {
        float s = 0.f;
        for (int i = 0; i < CH; i++) s += kp_s[i * NFsz + tid];
        g_z[(size_t)(bh * NCH + c) * NFsz + tid] = s;
    }
}

// ---------------------------------------------------------------------------
// Pass 2: in-place exclusive prefix over chunks for S and z, per (bh, elem).
// total threads = BHn * (NF*HD + NF) = 64 * 8320 = 532480 = 2080 * 256.
// ---------------------------------------------------------------------------
__global__ __launch_bounds__(256) void prefix_kernel()
{
    const int tid = blockIdx.x * 256 + threadIdx.x;
    const int total = BHn * (NFsz * HDsz + NFsz);
    if (tid >= total) return;
    const int bh = tid / (NFsz * HDsz + NFsz);
    const int r  = tid % (NFsz * HDsz + NFsz);
    float acc = 0.f;
    if (r < NFsz * HDsz) {
        float* p = g_S + (size_t)bh * NCH * NFsz * HDsz + r;
        for (int c = 0; c < NCH; c++) {
            float t = p[(size_t)c * NFsz * HDsz];
            p[(size_t)c * NFsz * HDsz] = acc;
            acc += t;
        }
    } else {
        float* p = g_z + (size_t)bh * NCH * NFsz + (r - NFsz * HDsz);
        for (int c = 0; c < NCH; c++) {
            float t = p[c * NFsz];
            p[c * NFsz] = acc;
            acc += t;
        }
    }
}

// ---------------------------------------------------------------------------
// Pass 3: per-chunk output.
//   A[i][j] = qp_i . kp_j  (j<=i, within chunk)
//   y_i     = (A @ v + qp_i @ S_prev) / (rowsum(A) + qp_i.z_prev + EPS)
// grid (NCH, BHn), 256 threads, ~133 KB dynamic smem.
// ---------------------------------------------------------------------------
__global__ __launch_bounds__(256) void chunk_out_kernel()
{
    extern __shared__ float sm[];
    float* qp_s  = sm;                     // 64 x (stride 129)
    float* kp_s  = qp_s + CH * 129;        // 64 x 129
    float* v_s   = kp_s + CH * 129;        // 64 x (stride 65)
    float* S_s   = v_s  + CH * 65;         // 128 x 65
    float* A_s   = S_s  + NFsz * 65;       // 64 x 65
    float* z_s   = A_s  + CH * 65;         // 128
    float* den_s = z_s  + NFsz;            // 64

    const int c = blockIdx.x, bh = blockIdx.y;
    const int tid = threadIdx.x;

    const float* qp = g_qp + (size_t)(bh * Tsz + c * CH) * NFsz;
    const float* kp = g_kp + (size_t)(bh * Tsz + c * CH) * NFsz;
    const float* vv = g_v  + (size_t)(bh * Tsz + c * CH) * HDsz;
    const float* Sg = g_S  + (size_t)(bh * NCH + c) * NFsz * HDsz;
    const float* zg = g_z  + (size_t)(bh * NCH + c) * NFsz;

    for (int i = tid; i < CH * NFsz; i += 256) {
        const int r = i >> 7, col = i & 127;
        qp_s[r * 129 + col] = qp[i];
        kp_s[r * 129 + col] = kp[i];
    }
    for (int i = tid; i < CH * HDsz; i += 256) {
        const int r = i >> 6, col = i & 63;
        v_s[r * 65 + col] = vv[i];
    }
    for (int i = tid; i < NFsz * HDsz; i += 256) {
        const int r = i >> 6, col = i & 63;
        S_s[r * 65 + col] = Sg[i];
    }
    if (tid < NFsz) z_s[tid] = zg[tid];
    __syncthreads();

    // Phase A: masked A = qp @ kp^T
    {
        const int ti = tid >> 4, tj = tid & 15;
        float acc[4][4] = {};
        for (int d = 0; d < NFsz; d++) {
            float qv[4], kv[4];
            #pragma unroll
            for (int ii = 0; ii < 4; ii++) qv[ii] = qp_s[(ti * 4 + ii) * 129 + d];
            #pragma unroll
            for (int jj = 0; jj < 4; jj++) kv[jj] = kp_s[(tj * 4 + jj) * 129 + d];
            #pragma unroll
            for (int ii = 0; ii < 4; ii++)
                #pragma unroll
                for (int jj = 0; jj < 4; jj++) acc[ii][jj] += qv[ii] * kv[jj];
        }
        #pragma unroll
        for (int ii = 0; ii < 4; ii++)
            #pragma unroll
            for (int jj = 0; jj < 4; jj++) {
                const int i = ti * 4 + ii, j = tj * 4 + jj;
                A_s[i * 65 + j] = (j <= i) ? acc[ii][jj] : 0.f;
            }
    }
    __syncthreads();

    // Denominator: rowsum(A) + qp.z_prev + EPS
    if (tid < CH) {
        float s = EPSv;
        for (int j = 0; j < CH; j++) s += A_s[tid * 65 + j];
        for (int d = 0; d < NFsz; d++) s += qp_s[tid * 129 + d] * z_s[d];
        den_s[tid] = s;
    }
    __syncthreads();

    // Phase B: y = (A @ v + qp @ S_prev) / den
    const int ti = tid >> 4, te = tid & 15;
    float acc[4][4] = {};
    for (int j = 0; j < CH; j++) {
        float av[4], vr[4];
        #pragma unroll
        for (int ii = 0; ii < 4; ii++) av[ii] = A_s[(ti * 4 + ii) * 65 + j];
        #pragma unroll
        for (int ee = 0; ee < 4; ee++) vr[ee] = v_s[j * 65 + te * 4 + ee];
        #pragma unroll
        for (int ii = 0; ii < 4; ii++)
            #pragma unroll
            for (int ee = 0; ee < 4; ee++) acc[ii][ee] += av[ii] * vr[ee];
    }
    for (int d = 0; d < NFsz; d++) {
        float qv[4], sv[4];
        #pragma unroll
        for (int ii = 0; ii < 4; ii++) qv[ii] = qp_s[(ti * 4 + ii) * 129 + d];
        #pragma unroll
        for (int ee = 0; ee < 4; ee++) sv[ee] = S_s[d * 65 + te * 4 + ee];
        #pragma unroll
        for (int ii = 0; ii < 4; ii++)
            #pragma unroll
            for (int ee = 0; ee < 4; ee++) acc[ii][ee] += qv[ii] * sv[ee];
    }

    const int b = bh >> 4, h = bh & 15;
    #pragma unroll
    for (int ii = 0; ii < 4; ii++) {
        const int i = ti * 4 + ii;
        const int t = c * CH + i;
        const float inv_den = 1.0f / den_s[i];
        #pragma unroll
        for (int ee = 0; ee < 4; ee++) {
            const int e = te * 4 + ee;
            g_y[((size_t)(b * Tsz + t)) * (Hn * HDsz) + h * HDsz + e] = acc[ii][ee] * inv_den;
        }
    }
}

// ---------------------------------------------------------------------------
extern "C" void kernel_launch(void* const* d_in, const int* in_sizes, int n_in,
                              void* d_out, int out_size)
{
    const float* x  = (const float*)d_in[0];
    const float* Wq = (const float*)d_in[1];
    const float* Wk = (const float*)d_in[2];
    const float* Wv = (const float*)d_in[3];
    const float* Wo = (const float*)d_in[4];
    const float* Wf = (const float*)d_in[5];
    float* out = (float*)d_out;

    float *q, *k, *v, *qp, *kp, *y;
    cudaGetSymbolAddress((void**)&q,  g_q);
    cudaGetSymbolAddress((void**)&k,  g_k);
    cudaGetSymbolAddress((void**)&v,  g_v);
    cudaGetSymbolAddress((void**)&qp, g_qp);
    cudaGetSymbolAddress((void**)&kp, g_kp);
    cudaGetSymbolAddress((void**)&y,  g_y);

    cudaFuncSetAttribute(chunk_out_kernel,
                         cudaFuncAttributeMaxDynamicSharedMemorySize, 136000);

    const dim3 ggrid(DM / 128, M_ROWS / 128);   // (8, 64)

    // QKV projections into head-major layout
    sgemm_kernel<true><<<ggrid, 256>>>(x, Wq, q, M_ROWS, DM, DM);
    sgemm_kernel<true><<<ggrid, 256>>>(x, Wk, k, M_ROWS, DM, DM);
    sgemm_kernel<true><<<ggrid, 256>>>(x, Wv, v, M_ROWS, DM, DM);

    // FAVOR+ feature maps
    featmap_kernel<<<(BHn * Tsz) / 64, 256>>>(q, Wf, qp);
    featmap_kernel<<<(BHn * Tsz) / 64, 256>>>(k, Wf, kp);

    // Chunked causal linear attention
    chunk_sums_kernel<<<dim3(NCH, BHn), 256>>>();
    prefix_kernel<<<2080, 256>>>();
    const size_t smem_bytes = (size_t)(CH * 129 * 2 + CH * 65 + NFsz * 65 + CH * 65 + NFsz + CH) * sizeof(float);
    chunk_out_kernel<<<dim3(NCH, BHn), 256, smem_bytes>>>();

    // Output projection
    sgemm_kernel<false><<<ggrid, 256>>>(y, Wo, out, M_ROWS, DM, DM);
}

// round 3
// speedup vs baseline: 1.8259x; 1.8259x over previous
#include <cuda_runtime.h>
#include <math.h>

// Problem constants
#define Bsz   4
#define Tsz   2048
#define DM    1024
#define Hn    16
#define HDsz  64
#define NFsz  128
#define CH    64              // chunk size for chunked causal linear attention
#define NCH   (Tsz / CH)      // 32 chunks
#define BHn   (Bsz * Hn)      // 64 (b,h) sequences
#define EPSv  1e-6f
#define INV_SQRT_NF 0.08838834764831845f  // 1/sqrt(128)

#define M_ROWS (Bsz * Tsz)    // 8192

// -------------------- scratch (device globals; no allocation allowed) ------
__device__ float g_q [BHn * Tsz * HDsz];   // (b,h,t,d)
__device__ float g_k [BHn * Tsz * HDsz];
__device__ float g_v [BHn * Tsz * HDsz];
__device__ float g_qp[BHn * Tsz * NFsz];   // (b,h,t,f)
__device__ float g_kp[BHn * Tsz * NFsz];
__device__ float g_S [BHn * NCH * NFsz * HDsz];  // per-chunk K^T V sums -> excl prefix
__device__ float g_z [BHn * NCH * NFsz];         // per-chunk k sums    -> excl prefix
__device__ float g_y [Bsz * Tsz * Hn * HDsz];    // (b,t,h,e) flat rows of 1024

// ---------------------------------------------------------------------------
// tf32 helpers
// ---------------------------------------------------------------------------
__device__ __forceinline__ unsigned f2tf32(float f) {
    unsigned u;
    asm("cvt.rna.tf32.f32 %0, %1;" : "=r"(u) : "f"(f));
    return u;
}

__device__ __forceinline__ void mma_tf32(float c[4],
                                         const unsigned a[4],
                                         const unsigned b[2]) {
    asm volatile(
        "mma.sync.aligned.m16n8k8.row.col.f32.tf32.tf32.f32 "
        "{%0,%1,%2,%3}, {%4,%5,%6,%7}, {%8,%9}, {%0,%1,%2,%3};"
        : "+f"(c[0]), "+f"(c[1]), "+f"(c[2]), "+f"(c[3])
        : "r"(a[0]), "r"(a[1]), "r"(a[2]), "r"(a[3]),
          "r"(b[0]), "r"(b[1]));
}

// ---------------------------------------------------------------------------
// TF32 tensor-core GEMM: C = A(MxK) * B(KxN), row-major.
// BM=BN=128, BK=16; 256 threads = 8 warps in 2x4 grid, 64x32 warp tile.
// Double-buffered smem, one __syncthreads per K-step.
// HEAD_OUT=true writes C in (b,h,t,d) head-major layout for q/k/v.
// ---------------------------------------------------------------------------
#define BKk 16
#define SMS 136   // smem row stride (floats): conflict-free fragment reads

template <bool HEAD_OUT>
__global__ __launch_bounds__(256) void tf32_gemm_kernel(
    const float* __restrict__ A, const float* __restrict__ B,
    float* __restrict__ C, int M, int N, int K)
{
    __shared__ unsigned As[2][BKk][SMS];
    __shared__ unsigned Bs[2][BKk][SMS];

    const int tid  = threadIdx.x;
    const int bRow = blockIdx.y, bCol = blockIdx.x;

    const int wid = tid >> 5, lane = tid & 31;
    const int wm = wid >> 2, wn = wid & 3;        // warp grid 2x4
    const int g  = lane >> 2, tg = lane & 3;      // fragment coords

    // global load mapping
    const int rA = tid >> 2;                      // 0..63 (and +64)
    const int cA = (tid & 3) * 4;                 // 0,4,8,12
    const int rB = tid >> 5;                      // 0..7 (and +8)
    const int cB = (tid & 31) * 4;                // 0..124

    const float* Ag = A + (size_t)bRow * 128 * K;
    const float* Bg = B + (size_t)bCol * 128;

    float acc[4][4][4] = {};                      // [mt][nt][frag]

    // prologue: load tile 0
    {
        float4 a0 = *reinterpret_cast<const float4*>(Ag + (size_t)rA * K + cA);
        float4 a1 = *reinterpret_cast<const float4*>(Ag + (size_t)(rA + 64) * K + cA);
        float4 b0 = *reinterpret_cast<const float4*>(Bg + (size_t)rB * N + cB);
        float4 b1 = *reinterpret_cast<const float4*>(Bg + (size_t)(rB + 8) * N + cB);
        As[0][cA + 0][rA] = f2tf32(a0.x);  As[0][cA + 1][rA] = f2tf32(a0.y);
        As[0][cA + 2][rA] = f2tf32(a0.z);  As[0][cA + 3][rA] = f2tf32(a0.w);
        As[0][cA + 0][rA + 64] = f2tf32(a1.x);  As[0][cA + 1][rA + 64] = f2tf32(a1.y);
        As[0][cA + 2][rA + 64] = f2tf32(a1.z);  As[0][cA + 3][rA + 64] = f2tf32(a1.w);
        uint4 ub0 = make_uint4(f2tf32(b0.x), f2tf32(b0.y), f2tf32(b0.z), f2tf32(b0.w));
        uint4 ub1 = make_uint4(f2tf32(b1.x), f2tf32(b1.y), f2tf32(b1.z), f2tf32(b1.w));
        *reinterpret_cast<uint4*>(&Bs[0][rB][cB])     = ub0;
        *reinterpret_cast<uint4*>(&Bs[0][rB + 8][cB]) = ub1;
    }
    __syncthreads();

    const int nk = K / BKk;
    for (int bk = 0; bk < nk; bk++) {
        const int cur = bk & 1;
        const bool has_next = (bk + 1) < nk;

        float4 pa0, pa1, pb0, pb1;
        if (has_next) {
            const int kofs = (bk + 1) * BKk;
            pa0 = *reinterpret_cast<const float4*>(Ag + (size_t)rA * K + kofs + cA);
            pa1 = *reinterpret_cast<const float4*>(Ag + (size_t)(rA + 64) * K + kofs + cA);
            pb0 = *reinterpret_cast<const float4*>(Bg + (size_t)(kofs + rB) * N + cB);
            pb1 = *reinterpret_cast<const float4*>(Bg + (size_t)(kofs + rB + 8) * N + cB);
        }

        // compute on current buffer: 2 k8-steps
        #pragma unroll
        for (int ks = 0; ks < 2; ks++) {
            const int k0 = ks * 8;
            unsigned af[4][4], bf[4][2];
            #pragma unroll
            for (int mt = 0; mt < 4; mt++) {
                const int mrow = wm * 64 + mt * 16 + g;
                af[mt][0] = As[cur][k0 + tg][mrow];
                af[mt][1] = As[cur][k0 + tg][mrow + 8];
                af[mt][2] = As[cur][k0 + tg + 4][mrow];
                af[mt][3] = As[cur][k0 + tg + 4][mrow + 8];
            }
            #pragma unroll
            for (int nt = 0; nt < 4; nt++) {
                const int ncol = wn * 32 + nt * 8 + g;
                bf[nt][0] = Bs[cur][k0 + tg][ncol];
                bf[nt][1] = Bs[cur][k0 + tg + 4][ncol];
            }
            #pragma unroll
            for (int mt = 0; mt < 4; mt++)
                #pragma unroll
                for (int nt = 0; nt < 4; nt++)
                    mma_tf32(acc[mt][nt], af[mt], bf[nt]);
        }

        if (has_next) {
            const int nxt = cur ^ 1;
            As[nxt][cA + 0][rA] = f2tf32(pa0.x);  As[nxt][cA + 1][rA] = f2tf32(pa0.y);
            As[nxt][cA + 2][rA] = f2tf32(pa0.z);  As[nxt][cA + 3][rA] = f2tf32(pa0.w);
            As[nxt][cA + 0][rA + 64] = f2tf32(pa1.x);  As[nxt][cA + 1][rA + 64] = f2tf32(pa1.y);
            As[nxt][cA + 2][rA + 64] = f2tf32(pa1.z);  As[nxt][cA + 3][rA + 64] = f2tf32(pa1.w);
            uint4 ub0 = make_uint4(f2tf32(pb0.x), f2tf32(pb0.y), f2tf32(pb0.z), f2tf32(pb0.w));
            uint4 ub1 = make_uint4(f2tf32(pb1.x), f2tf32(pb1.y), f2tf32(pb1.z), f2tf32(pb1.w));
            *reinterpret_cast<uint4*>(&Bs[nxt][rB][cB])     = ub0;
            *reinterpret_cast<uint4*>(&Bs[nxt][rB + 8][cB]) = ub1;
            __syncthreads();
        }
    }

    // epilogue
    #pragma unroll
    for (int mt = 0; mt < 4; mt++) {
        #pragma unroll
        for (int nt = 0; nt < 4; nt++) {
            const int n0 = bCol * 128 + wn * 32 + nt * 8 + 2 * tg;
            #pragma unroll
            for (int half = 0; half < 2; half++) {
                const int m = bRow * 128 + wm * 64 + mt * 16 + g + half * 8;
                float2 val = make_float2(acc[mt][nt][half * 2], acc[mt][nt][half * 2 + 1]);
                if (HEAD_OUT) {
                    const int b = m / Tsz, t = m % Tsz;
                    const int h = n0 >> 6, d = n0 & 63;
                    *reinterpret_cast<float2*>(
                        &C[(((size_t)(b * Hn + h)) * Tsz + t) * HDsz + d]) = val;
                } else {
                    *reinterpret_cast<float2*>(&C[(size_t)m * N + n0]) = val;
                }
            }
        }
    }
}

// ---------------------------------------------------------------------------
// Feature map: phi(x) = exp(x @ Wf - 0.5*||x||^2) * INV_SQRT_NF
// ---------------------------------------------------------------------------
__global__ __launch_bounds__(256) void featmap_kernel(
    const float* __restrict__ in, const float* __restrict__ Wf,
    float* __restrict__ out)
{
    __shared__ float Ws[HDsz * NFsz];   // 32 KB, [d][j]
    const int tid = threadIdx.x;
    for (int i = tid; i < HDsz * NFsz; i += 256) Ws[i] = Wf[i];
    __syncthreads();

    const int warp = tid >> 5, lane = tid & 31;
    const int row0 = blockIdx.x * 64 + warp * 8;

    for (int rr = 0; rr < 8; rr++) {
        const int r = row0 + rr;
        const float* q = in + (size_t)r * HDsz;
        const float q0 = q[lane], q1 = q[lane + 32];
        float v = q0 * q0 + q1 * q1;
        #pragma unroll
        for (int o = 16; o > 0; o >>= 1) v += __shfl_xor_sync(0xffffffffu, v, o);
        const float sq = 0.5f * v;

        float acc[4] = {0.f, 0.f, 0.f, 0.f};
        #pragma unroll
        for (int d = 0; d < 32; d++) {
            const float qd = __shfl_sync(0xffffffffu, q0, d);
            #pragma unroll
            for (int jj = 0; jj < 4; jj++) acc[jj] += qd * Ws[d * NFsz + lane + 32 * jj];
        }
        #pragma unroll
        for (int d = 0; d < 32; d++) {
            const float qd = __shfl_sync(0xffffffffu, q1, d);
            #pragma unroll
            for (int jj = 0; jj < 4; jj++) acc[jj] += qd * Ws[(d + 32) * NFsz + lane + 32 * jj];
        }
        #pragma unroll
        for (int jj = 0; jj < 4; jj++)
            out[(size_t)r * NFsz + lane + 32 * jj] = expf(acc[jj] - sq) * INV_SQRT_NF;
    }
}

// ---------------------------------------------------------------------------
// Pass 1: per-chunk state sums  S_c = kp_c^T @ v_c  (NFxHD), z_c = sum kp_c
// ---------------------------------------------------------------------------
__global__ __launch_bounds__(256) void chunk_sums_kernel()
{
    __shared__ float kp_s[CH * NFsz];  // 32 KB
    __shared__ float v_s [CH * HDsz];  // 16 KB
    const int c = blockIdx.x, bh = blockIdx.y;
    const int tid = threadIdx.x;

    const float* kp = g_kp + (size_t)(bh * Tsz + c * CH) * NFsz;
    const float* vv = g_v  + (size_t)(bh * Tsz + c * CH) * HDsz;
    for (int i = tid; i < CH * NFsz; i += 256) kp_s[i] = kp[i];
    for (int i = tid; i < CH * HDsz; i += 256) v_s[i]  = vv[i];
    __syncthreads();

    const int d0 = (tid >> 3) * 4;   // 32 d-groups of 4
    const int e0 = (tid & 7) * 8;    // 8 e-groups of 8
    float acc[4][8] = {};
    for (int i = 0; i < CH; i++) {
        float kk[4], vr[8];
        #pragma unroll
        for (int dd = 0; dd < 4; dd++) kk[dd] = kp_s[i * NFsz + d0 + dd];
        #pragma unroll
        for (int ee = 0; ee < 8; ee++) vr[ee] = v_s[i * HDsz + e0 + ee];
        #pragma unroll
        for (int dd = 0; dd < 4; dd++)
            #pragma unroll
            for (int ee = 0; ee < 8; ee++) acc[dd][ee] += kk[dd] * vr[ee];
    }
    float* Sout = g_S + (size_t)(bh * NCH + c) * NFsz * HDsz;
    #pragma unroll
    for (int dd = 0; dd < 4; dd++)
        #pragma unroll
        for (int ee = 0; ee < 8; ee++)
            Sout[(d0 + dd) * HDsz + e0 + ee] = acc[dd][ee];

    if (tid < NFsz) {
        float s = 0.f;
        for (int i = 0; i < CH; i++) s += kp_s[i * NFsz + tid];
        g_z[(size_t)(bh * NCH + c) * NFsz + tid] = s;
    }
}

// ---------------------------------------------------------------------------
// Pass 2: in-place exclusive prefix over chunks for S and z.
// ---------------------------------------------------------------------------
__global__ __launch_bounds__(256) void prefix_kernel()
{
    const int tid = blockIdx.x * 256 + threadIdx.x;
    const int total = BHn * (NFsz * HDsz + NFsz);
    if (tid >= total) return;
    const int bh = tid / (NFsz * HDsz + NFsz);
    const int r  = tid % (NFsz * HDsz + NFsz);
    float acc = 0.f;
    if (r < NFsz * HDsz) {
        float* p = g_S + (size_t)bh * NCH * NFsz * HDsz + r;
        for (int c = 0; c < NCH; c++) {
            float t = p[(size_t)c * NFsz * HDsz];
            p[(size_t)c * NFsz * HDsz] = acc;
            acc += t;
        }
    } else {
        float* p = g_z + (size_t)bh * NCH * NFsz + (r - NFsz * HDsz);
        for (int c = 0; c < NCH; c++) {
            float t = p[c * NFsz];
            p[c * NFsz] = acc;
            acc += t;
        }
    }
}

// ---------------------------------------------------------------------------
// Pass 3: per-chunk output.
// ---------------------------------------------------------------------------
__global__ __launch_bounds__(256) void chunk_out_kernel()
{
    extern __shared__ float sm[];
    float* qp_s  = sm;                     // 64 x (stride 129)
    float* kp_s  = qp_s + CH * 129;        // 64 x 129
    float* v_s   = kp_s + CH * 129;        // 64 x (stride 65)
    float* S_s   = v_s  + CH * 65;         // 128 x 65
    float* A_s   = S_s  + NFsz * 65;       // 64 x 65
    float* z_s   = A_s  + CH * 65;         // 128
    float* den_s = z_s  + NFsz;            // 64

    const int c = blockIdx.x, bh = blockIdx.y;
    const int tid = threadIdx.x;

    const float* qp = g_qp + (size_t)(bh * Tsz + c * CH) * NFsz;
    const float* kp = g_kp + (size_t)(bh * Tsz + c * CH) * NFsz;
    const float* vv = g_v  + (size_t)(bh * Tsz + c * CH) * HDsz;
    const float* Sg = g_S  + (size_t)(bh * NCH + c) * NFsz * HDsz;
    const float* zg = g_z  + (size_t)(bh * NCH + c) * NFsz;

    for (int i = tid; i < CH * NFsz; i += 256) {
        const int r = i >> 7, col = i & 127;
        qp_s[r * 129 + col] = qp[i];
        kp_s[r * 129 + col] = kp[i];
    }
    for (int i = tid; i < CH * HDsz; i += 256) {
        const int r = i >> 6, col = i & 63;
        v_s[r * 65 + col] = vv[i];
    }
    for (int i = tid; i < NFsz * HDsz; i += 256) {
        const int r = i >> 6, col = i & 63;
        S_s[r * 65 + col] = Sg[i];
    }
    if (tid < NFsz) z_s[tid] = zg[tid];
    __syncthreads();

    // Phase A: masked A = qp @ kp^T
    {
        const int ti = tid >> 4, tj = tid & 15;
        float acc[4][4] = {};
        for (int d = 0; d < NFsz; d++) {
            float qv[4], kv[4];
            #pragma unroll
            for (int ii = 0; ii < 4; ii++) qv[ii] = qp_s[(ti * 4 + ii) * 129 + d];
            #pragma unroll
            for (int jj = 0; jj < 4; jj++) kv[jj] = kp_s[(tj * 4 + jj) * 129 + d];
            #pragma unroll
            for (int ii = 0; ii < 4; ii++)
                #pragma unroll
                for (int jj = 0; jj < 4; jj++) acc[ii][jj] += qv[ii] * kv[jj];
        }
        #pragma unroll
        for (int ii = 0; ii < 4; ii++)
            #pragma unroll
            for (int jj = 0; jj < 4; jj++) {
                const int i = ti * 4 + ii, j = tj * 4 + jj;
                A_s[i * 65 + j] = (j <= i) ? acc[ii][jj] : 0.f;
            }
    }
    __syncthreads();

    // Denominator: rowsum(A) + qp.z_prev + EPS
    if (tid < CH) {
        float s = EPSv;
        for (int j = 0; j < CH; j++) s += A_s[tid * 65 + j];
        for (int d = 0; d < NFsz; d++) s += qp_s[tid * 129 + d] * z_s[d];
        den_s[tid] = s;
    }
    __syncthreads();

    // Phase B: y = (A @ v + qp @ S_prev) / den
    const int ti = tid >> 4, te = tid & 15;
    float acc[4][4] = {};
    for (int j = 0; j < CH; j++) {
        float av[4], vr[4];
        #pragma unroll
        for (int ii = 0; ii < 4; ii++) av[ii] = A_s[(ti * 4 + ii) * 65 + j];
        #pragma unroll
        for (int ee = 0; ee < 4; ee++) vr[ee] = v_s[j * 65 + te * 4 + ee];
        #pragma unroll
        for (int ii = 0; ii < 4; ii++)
            #pragma unroll
            for (int ee = 0; ee < 4; ee++) acc[ii][ee] += av[ii] * vr[ee];
    }
    for (int d = 0; d < NFsz; d++) {
        float qv[4], sv[4];
        #pragma unroll
        for (int ii = 0; ii < 4; ii++) qv[ii] = qp_s[(ti * 4 + ii) * 129 + d];
        #pragma unroll
        for (int ee = 0; ee < 4; ee++) sv[ee] = S_s[d * 65 + te * 4 + ee];
        #pragma unroll
        for (int ii = 0; ii < 4; ii++)
            #pragma unroll
            for (int ee = 0; ee < 4; ee++) acc[ii][ee] += qv[ii] * sv[ee];
    }

    const int b = bh >> 4, h = bh & 15;
    #pragma unroll
    for (int ii = 0; ii < 4; ii++) {
        const int i = ti * 4 + ii;
        const int t = c * CH + i;
        const float inv_den = 1.0f / den_s[i];
        #pragma unroll
        for (int ee = 0; ee < 4; ee++) {
            const int e = te * 4 + ee;
            g_y[((size_t)(b * Tsz + t)) * (Hn * HDsz) + h * HDsz + e] = acc[ii][ee] * inv_den;
        }
    }
}

// ---------------------------------------------------------------------------
extern "C" void kernel_launch(void* const* d_in, const int* in_sizes, int n_in,
                              void* d_out, int out_size)
{
    const float* x  = (const float*)d_in[0];
    const float* Wq = (const float*)d_in[1];
    const float* Wk = (const float*)d_in[2];
    const float* Wv = (const float*)d_in[3];
    const float* Wo = (const float*)d_in[4];
    const float* Wf = (const float*)d_in[5];
    float* out = (float*)d_out;

    float *q, *k, *v, *qp, *kp, *y;
    cudaGetSymbolAddress((void**)&q,  g_q);
    cudaGetSymbolAddress((void**)&k,  g_k);
    cudaGetSymbolAddress((void**)&v,  g_v);
    cudaGetSymbolAddress((void**)&qp, g_qp);
    cudaGetSymbolAddress((void**)&kp, g_kp);
    cudaGetSymbolAddress((void**)&y,  g_y);

    cudaFuncSetAttribute(chunk_out_kernel,
                         cudaFuncAttributeMaxDynamicSharedMemorySize, 136000);

    const dim3 ggrid(DM / 128, M_ROWS / 128);   // (8, 64)

    // QKV projections into head-major layout (tf32 tensor cores)
    tf32_gemm_kernel<true><<<ggrid, 256>>>(x, Wq, q, M_ROWS, DM, DM);
    tf32_gemm_kernel<true><<<ggrid, 256>>>(x, Wk, k, M_ROWS, DM, DM);
    tf32_gemm_kernel<true><<<ggrid, 256>>>(x, Wv, v, M_ROWS, DM, DM);

    // FAVOR+ feature maps
    featmap_kernel<<<(BHn * Tsz) / 64, 256>>>(q, Wf, qp);
    featmap_kernel<<<(BHn * Tsz) / 64, 256>>>(k, Wf, kp);

    // Chunked causal linear attention
    chunk_sums_kernel<<<dim3(NCH, BHn), 256>>>();
    prefix_kernel<<<2080, 256>>>();
    const size_t smem_bytes = (size_t)(CH * 129 * 2 + CH * 65 + NFsz * 65 + CH * 65 + NFsz + CH) * sizeof(float);
    chunk_out_kernel<<<dim3(NCH, BHn), 256, smem_bytes>>>();

    // Output projection (tf32 tensor cores)
    tf32_gemm_kernel<false><<<ggrid, 256>>>(y, Wo, out, M_ROWS, DM, DM);
}

// round 5
// speedup vs baseline: 1.8881x; 1.0340x over previous
#include <cuda_runtime.h>
#include <cuda_bf16.h>
#include <math.h>

// Problem constants
#define Bsz   4
#define Tsz   2048
#define DM    1024
#define Hn    16
#define HDsz  64
#define NFsz  128
#define CH    64
#define NCH   (Tsz / CH)      // 32
#define BHn   (Bsz * Hn)      // 64
#define EPSv  1e-6f
#define INV_SQRT_NF 0.08838834764831845f

#define M_ROWS (Bsz * Tsz)    // 8192
#define KP     (DM / 2)       // 512 k-pairs

// -------------------- scratch (device globals) -----------------------------
__device__ float g_q [BHn * Tsz * HDsz];
__device__ float g_k [BHn * Tsz * HDsz];
__device__ float g_v [BHn * Tsz * HDsz];
__device__ float g_qp[BHn * Tsz * NFsz];
__device__ float g_kp[BHn * Tsz * NFsz];
__device__ float g_S [BHn * NCH * NFsz * HDsz];
__device__ float g_z [BHn * NCH * NFsz];
__device__ float g_y [Bsz * Tsz * Hn * HDsz];

// bf16x2 packed operands: [KP][M] u32 (k-pair major), hi and lo residual
__device__ unsigned g_Xh[KP * M_ROWS];
__device__ unsigned g_Xl[KP * M_ROWS];
__device__ unsigned g_Wh[4 * KP * DM];
__device__ unsigned g_Wl[4 * KP * DM];

// ---------------------------------------------------------------------------
// helpers
// ---------------------------------------------------------------------------
__device__ __forceinline__ void bsplit2(float v0, float v1, unsigned& hi, unsigned& lo) {
    // pack(hi) = {bf16(v1)<<16 | bf16(v0)}; lo = residual pair. low half = even-k elem.
    __nv_bfloat16 h0 = __float2bfloat16_rn(v0);
    __nv_bfloat16 h1 = __float2bfloat16_rn(v1);
    float r0 = v0 - __bfloat162float(h0);
    float r1 = v1 - __bfloat162float(h1);
    __nv_bfloat16 l0 = __float2bfloat16_rn(r0);
    __nv_bfloat16 l1 = __float2bfloat16_rn(r1);
    hi = ((unsigned)__bfloat16_as_ushort(h1) << 16) | __bfloat16_as_ushort(h0);
    lo = ((unsigned)__bfloat16_as_ushort(l1) << 16) | __bfloat16_as_ushort(l0);
}

__device__ __forceinline__ void mma_bf16(float c[4], const unsigned a[4], const unsigned b[2]) {
    asm volatile(
        "mma.sync.aligned.m16n8k16.row.col.f32.bf16.bf16.f32 "
        "{%0,%1,%2,%3}, {%4,%5,%6,%7}, {%8,%9}, {%0,%1,%2,%3};"
        : "+f"(c[0]), "+f"(c[1]), "+f"(c[2]), "+f"(c[3])
        : "r"(a[0]), "r"(a[1]), "r"(a[2]), "r"(a[3]), "r"(b[0]), "r"(b[1]));
}

#define CP16(dst, src) \
    asm volatile("cp.async.cg.shared.global [%0], [%1], 16;" :: "r"(dst), "l"(src))
#define CP_COMMIT() asm volatile("cp.async.commit_group;")
#define CP_WAIT1()  asm volatile("cp.async.wait_group 1;")

// ---------------------------------------------------------------------------
// pack_w: W (DM x DM f32, k-major rows) -> Wh/Wl [KP][DM] u32
// ---------------------------------------------------------------------------
__global__ __launch_bounds__(256) void pack_w_kernel(
    const float* __restrict__ W, unsigned* __restrict__ Wh, unsigned* __restrict__ Wl)
{
    const int idx = blockIdx.x * 256 + threadIdx.x;   // over KP*DM
    const int kp = idx >> 10, n = idx & 1023;
    const float v0 = W[(size_t)(2 * kp) * DM + n];
    const float v1 = W[(size_t)(2 * kp + 1) * DM + n];
    unsigned hi, lo;
    bsplit2(v0, v1, hi, lo);
    Wh[idx] = hi;  Wl[idx] = lo;
}

// ---------------------------------------------------------------------------
// pack_x: X (M x DM f32 row-major) -> Xh/Xl [KP][M] u32 (transposed pack)
// block: 64 m x 32 kp. grid (M/64, KP/32)
// ---------------------------------------------------------------------------
__global__ __launch_bounds__(256) void pack_x_kernel(
    const float* __restrict__ X, unsigned* __restrict__ Xh, unsigned* __restrict__ Xl)
{
    __shared__ unsigned smh[32 * 65];
    __shared__ unsigned sml[32 * 65];
    const int tid = threadIdx.x;
    const int m0 = blockIdx.x * 64, kp0 = blockIdx.y * 32;

    #pragma unroll
    for (int it = 0; it < 8; it++) {
        const int idx = it * 256 + tid;
        const int kp_l = idx & 31, m_l = idx >> 5;
        const float2 v = *reinterpret_cast<const float2*>(
            X + (size_t)(m0 + m_l) * DM + 2 * (kp0 + kp_l));
        unsigned hi, lo;
        bsplit2(v.x, v.y, hi, lo);
        smh[kp_l * 65 + m_l] = hi;
        sml[kp_l * 65 + m_l] = lo;
    }
    __syncthreads();
    #pragma unroll
    for (int it = 0; it < 8; it++) {
        const int idx = it * 256 + tid;
        const int kp_l = idx >> 6, m_l = idx & 63;
        Xh[(size_t)(kp0 + kp_l) * M_ROWS + m0 + m_l] = smh[kp_l * 65 + m_l];
        Xl[(size_t)(kp0 + kp_l) * M_ROWS + m0 + m_l] = sml[kp_l * 65 + m_l];
    }
}

// ---------------------------------------------------------------------------
// bf16x2 tensor-core GEMM: C = A(MxK) * B(KxN), K=1024 (KP=512 pairs).
// A,B given as packed hi/lo [KP][M] / [KP][N] u32. BM=BN=128, BK=16 (8 kp).
// 3-stage cp.async pipeline. 8 warps (2x4), 64x32 warp tiles.
// C += Ahi*Bhi + Ahi*Blo + Alo*Bhi.
// ---------------------------------------------------------------------------
#define SMS 136                      // u32 row stride (conflict-free frags, 16B aligned)
#define STAGE_U32 (4 * 8 * SMS)      // Ah,Al,Bh,Bl tiles per stage = 4352
#define GEMM_SMEM_BYTES (3 * STAGE_U32 * 4)   // 52224

template <bool HEAD_OUT>
__global__ __launch_bounds__(256) void bf16x2_gemm_kernel(
    const unsigned* __restrict__ Ah, const unsigned* __restrict__ Al,
    const unsigned* __restrict__ Bh, const unsigned* __restrict__ Bl,
    float* __restrict__ C, int M, int N)
{
    extern __shared__ unsigned sm[];

    const int tid  = threadIdx.x;
    const int bRow = blockIdx.y, bCol = blockIdx.x;
    const int wid = tid >> 5, lane = tid & 31;
    const int wm = wid >> 2, wn = wid & 3;
    const int g  = lane >> 2, tg = lane & 3;

    const int lrow = tid >> 5;            // 0..7 (kp row within slab)
    const int lseg = tid & 31;            // 16B segment
    const size_t mA = (size_t)bRow * 128 + lseg * 4;
    const size_t nB = (size_t)bCol * 128 + lseg * 4;

    const unsigned dst_base = (unsigned)__cvta_generic_to_shared(sm);
    const unsigned dst_off  = (lrow * SMS + lseg * 4) * 4;  // bytes within a tile

    auto issue = [&](int st, int s) {
        const size_t kpr = (size_t)(s * 8 + lrow);
        const unsigned d0 = dst_base + st * STAGE_U32 * 4 + dst_off;
        CP16(d0,                       Ah + kpr * M + mA);
        CP16(d0 + 8 * SMS * 4,         Al + kpr * M + mA);
        CP16(d0 + 16 * SMS * 4,        Bh + kpr * N + nB);
        CP16(d0 + 24 * SMS * 4,        Bl + kpr * N + nB);
    };

    float acc[4][4][4] = {};

    issue(0, 0); CP_COMMIT();
    issue(1, 1); CP_COMMIT();

    const int NSLAB = 64;   // 512 kp / 8
    for (int s = 0; s < NSLAB; s++) {
        CP_WAIT1();
        __syncthreads();
        if (s + 2 < NSLAB) issue((s + 2) % 3, s + 2);
        CP_COMMIT();

        const unsigned* Sb = sm + (s % 3) * STAGE_U32;
        const unsigned* SAh = Sb;
        const unsigned* SAl = Sb + 8 * SMS;
        const unsigned* SBh = Sb + 16 * SMS;
        const unsigned* SBl = Sb + 24 * SMS;

        unsigned a[4][4], bh[4][2], bl[4][2];
        #pragma unroll
        for (int mt = 0; mt < 4; mt++) {
            const int mrow = wm * 64 + mt * 16 + g;
            a[mt][0] = SAh[tg * SMS + mrow];
            a[mt][1] = SAh[tg * SMS + mrow + 8];
            a[mt][2] = SAh[(tg + 4) * SMS + mrow];
            a[mt][3] = SAh[(tg + 4) * SMS + mrow + 8];
        }
        #pragma unroll
        for (int nt = 0; nt < 4; nt++) {
            const int ncol = wn * 32 + nt * 8 + g;
            bh[nt][0] = SBh[tg * SMS + ncol];
            bh[nt][1] = SBh[(tg + 4) * SMS + ncol];
            bl[nt][0] = SBl[tg * SMS + ncol];
            bl[nt][1] = SBl[(tg + 4) * SMS + ncol];
        }
        // hi*hi
        #pragma unroll
        for (int mt = 0; mt < 4; mt++)
            #pragma unroll
            for (int nt = 0; nt < 4; nt++) mma_bf16(acc[mt][nt], a[mt], bh[nt]);
        // hi*lo
        #pragma unroll
        for (int mt = 0; mt < 4; mt++)
            #pragma unroll
            for (int nt = 0; nt < 4; nt++) mma_bf16(acc[mt][nt], a[mt], bl[nt]);
        // lo*hi (overwrite a with Alo)
        #pragma unroll
        for (int mt = 0; mt < 4; mt++) {
            const int mrow = wm * 64 + mt * 16 + g;
            a[mt][0] = SAl[tg * SMS + mrow];
            a[mt][1] = SAl[tg * SMS + mrow + 8];
            a[mt][2] = SAl[(tg + 4) * SMS + mrow];
            a[mt][3] = SAl[(tg + 4) * SMS + mrow + 8];
        }
        #pragma unroll
        for (int mt = 0; mt < 4; mt++)
            #pragma unroll
            for (int nt = 0; nt < 4; nt++) mma_bf16(acc[mt][nt], a[mt], bh[nt]);
    }

    // epilogue
    #pragma unroll
    for (int mt = 0; mt < 4; mt++) {
        #pragma unroll
        for (int nt = 0; nt < 4; nt++) {
            const int n0 = bCol * 128 + wn * 32 + nt * 8 + 2 * tg;
            #pragma unroll
            for (int half = 0; half < 2; half++) {
                const int m = bRow * 128 + wm * 64 + mt * 16 + g + half * 8;
                float2 val = make_float2(acc[mt][nt][half * 2], acc[mt][nt][half * 2 + 1]);
                if (HEAD_OUT) {
                    const int b = m / Tsz, t = m % Tsz;
                    const int h = n0 >> 6, d = n0 & 63;
                    *reinterpret_cast<float2*>(
                        &C[(((size_t)(b * Hn + h)) * Tsz + t) * HDsz + d]) = val;
                } else {
                    *reinterpret_cast<float2*>(&C[(size_t)m * N + n0]) = val;
                }
            }
        }
    }
}

// ---------------------------------------------------------------------------
// Feature map: phi(x) = exp(x @ Wf - 0.5*||x||^2) * INV_SQRT_NF
// 4-row blocking: each Ws LDS feeds 16 FMAs.
// ---------------------------------------------------------------------------
__global__ __launch_bounds__(256) void featmap_kernel(
    const float* __restrict__ in, const float* __restrict__ Wf,
    float* __restrict__ out)
{
    __shared__ float Ws[HDsz * NFsz];
    const int tid = threadIdx.x;
    for (int i = tid; i < HDsz * NFsz; i += 256) Ws[i] = Wf[i];
    __syncthreads();

    const int warp = tid >> 5, lane = tid & 31;
    const int row0 = blockIdx.x * 64 + warp * 8;

    #pragma unroll
    for (int half = 0; half < 2; half++) {
        const int rbase = row0 + half * 4;
        float q0[4], q1[4], sq[4];
        #pragma unroll
        for (int rw = 0; rw < 4; rw++) {
            const float* qr = in + (size_t)(rbase + rw) * HDsz;
            q0[rw] = qr[lane];  q1[rw] = qr[lane + 32];
            float v = q0[rw] * q0[rw] + q1[rw] * q1[rw];
            #pragma unroll
            for (int o = 16; o > 0; o >>= 1) v += __shfl_xor_sync(0xffffffffu, v, o);
            sq[rw] = 0.5f * v;
        }
        float acc[4][4] = {};
        #pragma unroll
        for (int d = 0; d < 32; d++) {
            float ws[4];
            #pragma unroll
            for (int j = 0; j < 4; j++) ws[j] = Ws[d * NFsz + lane + 32 * j];
            #pragma unroll
            for (int rw = 0; rw < 4; rw++) {
                const float qd = __shfl_sync(0xffffffffu, q0[rw], d);
                #pragma unroll
                for (int j = 0; j < 4; j++) acc[rw][j] += qd * ws[j];
            }
        }
        #pragma unroll
        for (int d = 0; d < 32; d++) {
            float ws[4];
            #pragma unroll
            for (int j = 0; j < 4; j++) ws[j] = Ws[(d + 32) * NFsz + lane + 32 * j];
            #pragma unroll
            for (int rw = 0; rw < 4; rw++) {
                const float qd = __shfl_sync(0xffffffffu, q1[rw], d);
                #pragma unroll
                for (int j = 0; j < 4; j++) acc[rw][j] += qd * ws[j];
            }
        }
        #pragma unroll
        for (int rw = 0; rw < 4; rw++)
            #pragma unroll
            for (int j = 0; j < 4; j++)
                out[(size_t)(rbase + rw) * NFsz + lane + 32 * j] =
                    expf(acc[rw][j] - sq[rw]) * INV_SQRT_NF;
    }
}

// ---------------------------------------------------------------------------
// Pass 1: per-chunk state sums  S_c = kp_c^T @ v_c, z_c = sum kp_c
// ---------------------------------------------------------------------------
__global__ __launch_bounds__(256) void chunk_sums_kernel()
{
    __shared__ float kp_s[CH * NFsz];
    __shared__ float v_s [CH * HDsz];
    const int c = blockIdx.x, bh = blockIdx.y;
    const int tid = threadIdx.x;

    const float* kp = g_kp + (size_t)(bh * Tsz + c * CH) * NFsz;
    const float* vv = g_v  + (size_t)(bh * Tsz + c * CH) * HDsz;
    for (int i = tid; i < CH * NFsz; i += 256) kp_s[i] = kp[i];
    for (int i = tid; i < CH * HDsz; i += 256) v_s[i]  = vv[i];
    __syncthreads();

    const int d0 = (tid >> 3) * 4;
    const int e0 = (tid & 7) * 8;
    float acc[4][8] = {};
    for (int i = 0; i < CH; i++) {
        float kk[4], vr[8];
        #pragma unroll
        for (int dd = 0; dd < 4; dd++) kk[dd] = kp_s[i * NFsz + d0 + dd];
        #pragma unroll
        for (int ee = 0; ee < 8; ee++) vr[ee] = v_s[i * HDsz + e0 + ee];
        #pragma unroll
        for (int dd = 0; dd < 4; dd++)
            #pragma unroll
            for (int ee = 0; ee < 8; ee++) acc[dd][ee] += kk[dd] * vr[ee];
    }
    float* Sout = g_S + (size_t)(bh * NCH + c) * NFsz * HDsz;
    #pragma unroll
    for (int dd = 0; dd < 4; dd++)
        #pragma unroll
        for (int ee = 0; ee < 8; ee++)
            Sout[(d0 + dd) * HDsz + e0 + ee] = acc[dd][ee];

    if (tid < NFsz) {
        float s = 0.f;
        for (int i = 0; i < CH; i++) s += kp_s[i * NFsz + tid];
        g_z[(size_t)(bh * NCH + c) * NFsz + tid] = s;
    }
}

// ---------------------------------------------------------------------------
// Pass 2: exclusive prefix over chunks (in-place)
// ---------------------------------------------------------------------------
__global__ __launch_bounds__(256) void prefix_kernel()
{
    const int tid = blockIdx.x * 256 + threadIdx.x;
    const int total = BHn * (NFsz * HDsz + NFsz);
    if (tid >= total) return;
    const int bh = tid / (NFsz * HDsz + NFsz);
    const int r  = tid % (NFsz * HDsz + NFsz);
    float acc = 0.f;
    if (r < NFsz * HDsz) {
        float* p = g_S + (size_t)bh * NCH * NFsz * HDsz + r;
        for (int c = 0; c < NCH; c++) {
            float t = p[(size_t)c * NFsz * HDsz];
            p[(size_t)c * NFsz * HDsz] = acc;
            acc += t;
        }
    } else {
        float* p = g_z + (size_t)bh * NCH * NFsz + (r - NFsz * HDsz);
        for (int c = 0; c < NCH; c++) {
            float t = p[c * NFsz];
            p[c * NFsz] = acc;
            acc += t;
        }
    }
}

// ---------------------------------------------------------------------------
// Pass 3: per-chunk output
// ---------------------------------------------------------------------------
__global__ __launch_bounds__(256) void chunk_out_kernel()
{
    extern __shared__ float smf[];
    float* qp_s  = smf;
    float* kp_s  = qp_s + CH * 129;
    float* v_s   = kp_s + CH * 129;
    float* S_s   = v_s  + CH * 65;
    float* A_s   = S_s  + NFsz * 65;
    float* z_s   = A_s  + CH * 65;
    float* den_s = z_s  + NFsz;

    const int c = blockIdx.x, bh = blockIdx.y;
    const int tid = threadIdx.x;

    const float* qp = g_qp + (size_t)(bh * Tsz + c * CH) * NFsz;
    const float* kp = g_kp + (size_t)(bh * Tsz + c * CH) * NFsz;
    const float* vv = g_v  + (size_t)(bh * Tsz + c * CH) * HDsz;
    const float* Sg = g_S  + (size_t)(bh * NCH + c) * NFsz * HDsz;
    const float* zg = g_z  + (size_t)(bh * NCH + c) * NFsz;

    for (int i = tid; i < CH * NFsz; i += 256) {
        const int r = i >> 7, col = i & 127;
        qp_s[r * 129 + col] = qp[i];
        kp_s[r * 129 + col] = kp[i];
    }
    for (int i = tid; i < CH * HDsz; i += 256) {
        const int r = i >> 6, col = i & 63;
        v_s[r * 65 + col] = vv[i];
    }
    for (int i = tid; i < NFsz * HDsz; i += 256) {
        const int r = i >> 6, col = i & 63;
        S_s[r * 65 + col] = Sg[i];
    }
    if (tid < NFsz) z_s[tid] = zg[tid];
    __syncthreads();

    {
        const int ti = tid >> 4, tj = tid & 15;
        float acc[4][4] = {};
        for (int d = 0; d < NFsz; d++) {
            float qv[4], kv[4];
            #pragma unroll
            for (int ii = 0; ii < 4; ii++) qv[ii] = qp_s[(ti * 4 + ii) * 129 + d];
            #pragma unroll
            for (int jj = 0; jj < 4; jj++) kv[jj] = kp_s[(tj * 4 + jj) * 129 + d];
            #pragma unroll
            for (int ii = 0; ii < 4; ii++)
                #pragma unroll
                for (int jj = 0; jj < 4; jj++) acc[ii][jj] += qv[ii] * kv[jj];
        }
        #pragma unroll
        for (int ii = 0; ii < 4; ii++)
            #pragma unroll
            for (int jj = 0; jj < 4; jj++) {
                const int i = ti * 4 + ii, j = tj * 4 + jj;
                A_s[i * 65 + j] = (j <= i) ? acc[ii][jj] : 0.f;
            }
    }
    __syncthreads();

    if (tid < CH) {
        float s = EPSv;
        for (int j = 0; j < CH; j++) s += A_s[tid * 65 + j];
        for (int d = 0; d < NFsz; d++) s += qp_s[tid * 129 + d] * z_s[d];
        den_s[tid] = s;
    }
    __syncthreads();

    const int ti = tid >> 4, te = tid & 15;
    float acc[4][4] = {};
    for (int j = 0; j < CH; j++) {
        float av[4], vr[4];
        #pragma unroll
        for (int ii = 0; ii < 4; ii++) av[ii] = A_s[(ti * 4 + ii) * 65 + j];
        #pragma unroll
        for (int ee = 0; ee < 4; ee++) vr[ee] = v_s[j * 65 + te * 4 + ee];
        #pragma unroll
        for (int ii = 0; ii < 4; ii++)
            #pragma unroll
            for (int ee = 0; ee < 4; ee++) acc[ii][ee] += av[ii] * vr[ee];
    }
    for (int d = 0; d < NFsz; d++) {
        float qv[4], sv[4];
        #pragma unroll
        for (int ii = 0; ii < 4; ii++) qv[ii] = qp_s[(ti * 4 + ii) * 129 + d];
        #pragma unroll
        for (int ee = 0; ee < 4; ee++) sv[ee] = S_s[d * 65 + te * 4 + ee];
        #pragma unroll
        for (int ii = 0; ii < 4; ii++)
            #pragma unroll
            for (int ee = 0; ee < 4; ee++) acc[ii][ee] += qv[ii] * sv[ee];
    }

    const int b = bh >> 4, h = bh & 15;
    #pragma unroll
    for (int ii = 0; ii < 4; ii++) {
        const int i = ti * 4 + ii;
        const int t = c * CH + i;
        const float inv_den = 1.0f / den_s[i];
        #pragma unroll
        for (int ee = 0; ee < 4; ee++) {
            const int e = te * 4 + ee;
            g_y[((size_t)(b * Tsz + t)) * (Hn * HDsz) + h * HDsz + e] = acc[ii][ee] * inv_den;
        }
    }
}

// ---------------------------------------------------------------------------
extern "C" void kernel_launch(void* const* d_in, const int* in_sizes, int n_in,
                              void* d_out, int out_size)
{
    const float* x  = (const float*)d_in[0];
    const float* Wq = (const float*)d_in[1];
    const float* Wk = (const float*)d_in[2];
    const float* Wv = (const float*)d_in[3];
    const float* Wo = (const float*)d_in[4];
    const float* Wf = (const float*)d_in[5];
    float* out = (float*)d_out;

    float *q, *k, *v, *qp, *kp, *y;
    unsigned *Xh, *Xl, *Wh, *Wl;
    cudaGetSymbolAddress((void**)&q,  g_q);
    cudaGetSymbolAddress((void**)&k,  g_k);
    cudaGetSymbolAddress((void**)&v,  g_v);
    cudaGetSymbolAddress((void**)&qp, g_qp);
    cudaGetSymbolAddress((void**)&kp, g_kp);
    cudaGetSymbolAddress((void**)&y,  g_y);
    cudaGetSymbolAddress((void**)&Xh, g_Xh);
    cudaGetSymbolAddress((void**)&Xl, g_Xl);
    cudaGetSymbolAddress((void**)&Wh, g_Wh);
    cudaGetSymbolAddress((void**)&Wl, g_Wl);

    cudaFuncSetAttribute(chunk_out_kernel,
                         cudaFuncAttributeMaxDynamicSharedMemorySize, 136000);
    cudaFuncSetAttribute(bf16x2_gemm_kernel<true>,
                         cudaFuncAttributeMaxDynamicSharedMemorySize, GEMM_SMEM_BYTES);
    cudaFuncSetAttribute(bf16x2_gemm_kernel<false>,
                         cudaFuncAttributeMaxDynamicSharedMemorySize, GEMM_SMEM_BYTES);

    const int WSTRIDE = KP * DM;
    // pack weights (hi/lo bf16, k-pair packed)
    pack_w_kernel<<<(KP * DM) / 256, 256>>>(Wq, Wh + 0 * WSTRIDE, Wl + 0 * WSTRIDE);
    pack_w_kernel<<<(KP * DM) / 256, 256>>>(Wk, Wh + 1 * WSTRIDE, Wl + 1 * WSTRIDE);
    pack_w_kernel<<<(KP * DM) / 256, 256>>>(Wv, Wh + 2 * WSTRIDE, Wl + 2 * WSTRIDE);
    pack_w_kernel<<<(KP * DM) / 256, 256>>>(Wo, Wh + 3 * WSTRIDE, Wl + 3 * WSTRIDE);
    // pack activations (transposed)
    pack_x_kernel<<<dim3(M_ROWS / 64, KP / 32), 256>>>(x, Xh, Xl);

    const dim3 ggrid(DM / 128, M_ROWS / 128);   // (8, 64)
    bf16x2_gemm_kernel<true><<<ggrid, 256, GEMM_SMEM_BYTES>>>(
        Xh, Xl, Wh + 0 * WSTRIDE, Wl + 0 * WSTRIDE, q, M_ROWS, DM);
    bf16x2_gemm_kernel<true><<<ggrid, 256, GEMM_SMEM_BYTES>>>(
        Xh, Xl, Wh + 1 * WSTRIDE, Wl + 1 * WSTRIDE, k, M_ROWS, DM);
    bf16x2_gemm_kernel<true><<<ggrid, 256, GEMM_SMEM_BYTES>>>(
        Xh, Xl, Wh + 2 * WSTRIDE, Wl + 2 * WSTRIDE, v, M_ROWS, DM);

    featmap_kernel<<<(BHn * Tsz) / 64, 256>>>(q, Wf, qp);
    featmap_kernel<<<(BHn * Tsz) / 64, 256>>>(k, Wf, kp);

    chunk_sums_kernel<<<dim3(NCH, BHn), 256>>>();
    prefix_kernel<<<2080, 256>>>();
    const size_t smem_bytes = (size_t)(CH * 129 * 2 + CH * 65 + NFsz * 65 + CH * 65 + NFsz + CH) * sizeof(float);
    chunk_out_kernel<<<dim3(NCH, BHn), 256, smem_bytes>>>();

    // output projection: repack y (reuse Xh/Xl), then GEMM
    pack_x_kernel<<<dim3(M_ROWS / 64, KP / 32), 256>>>(y, Xh, Xl);
    bf16x2_gemm_kernel<false><<<ggrid, 256, GEMM_SMEM_BYTES>>>(
        Xh, Xl, Wh + 3 * WSTRIDE, Wl + 3 * WSTRIDE, out, M_ROWS, DM);
}

// round 6
// speedup vs baseline: 1.9780x; 1.0476x over previous
#include <cuda_runtime.h>
#include <cuda_bf16.h>
#include <math.h>

// Problem constants
#define Bsz   4
#define Tsz   2048
#define DM    1024
#define Hn    16
#define HDsz  64
#define NFsz  128
#define CH    64
#define NCH   (Tsz / CH)      // 32
#define BHn   (Bsz * Hn)      // 64
#define EPSv  1e-6f
#define INV_SQRT_NF 0.08838834764831845f

#define M_ROWS (Bsz * Tsz)    // 8192
#define KP     (DM / 2)       // 512 k-pairs
#define FROWS  (BHn * Tsz)    // 131072 feature rows

// -------------------- scratch (device globals) -----------------------------
__device__ float g_q [BHn * Tsz * HDsz];
__device__ float g_k [BHn * Tsz * HDsz];
__device__ float g_v [BHn * Tsz * HDsz];
__device__ float g_qp[BHn * Tsz * NFsz];
__device__ float g_kp[BHn * Tsz * NFsz];
__device__ float g_S [BHn * NCH * NFsz * HDsz];
__device__ float g_z [BHn * NCH * NFsz];
__device__ float g_y [Bsz * Tsz * Hn * HDsz];

__device__ unsigned g_Xh[KP * M_ROWS];
__device__ unsigned g_Xl[KP * M_ROWS];
__device__ unsigned g_Wh[4 * KP * DM];
__device__ unsigned g_Wl[4 * KP * DM];

// ---------------------------------------------------------------------------
// helpers
// ---------------------------------------------------------------------------
__device__ __forceinline__ void bsplit2(float v0, float v1, unsigned& hi, unsigned& lo) {
    __nv_bfloat16 h0 = __float2bfloat16_rn(v0);
    __nv_bfloat16 h1 = __float2bfloat16_rn(v1);
    float r0 = v0 - __bfloat162float(h0);
    float r1 = v1 - __bfloat162float(h1);
    __nv_bfloat16 l0 = __float2bfloat16_rn(r0);
    __nv_bfloat16 l1 = __float2bfloat16_rn(r1);
    hi = ((unsigned)__bfloat16_as_ushort(h1) << 16) | __bfloat16_as_ushort(h0);
    lo = ((unsigned)__bfloat16_as_ushort(l1) << 16) | __bfloat16_as_ushort(l0);
}

__device__ __forceinline__ void mma_bf16(float c[4], const unsigned a[4], const unsigned b[2]) {
    asm volatile(
        "mma.sync.aligned.m16n8k16.row.col.f32.bf16.bf16.f32 "
        "{%0,%1,%2,%3}, {%4,%5,%6,%7}, {%8,%9}, {%0,%1,%2,%3};"
        : "+f"(c[0]), "+f"(c[1]), "+f"(c[2]), "+f"(c[3])
        : "r"(a[0]), "r"(a[1]), "r"(a[2]), "r"(a[3]), "r"(b[0]), "r"(b[1]));
}

#define CP16(dst, src) \
    asm volatile("cp.async.cg.shared.global [%0], [%1], 16;" :: "r"(dst), "l"(src))
#define CP_COMMIT() asm volatile("cp.async.commit_group;")
#define CP_WAIT1()  asm volatile("cp.async.wait_group 1;")

// ---------------------------------------------------------------------------
// pack_w / pack_x (unchanged)
// ---------------------------------------------------------------------------
__global__ __launch_bounds__(256) void pack_w_kernel(
    const float* __restrict__ W, unsigned* __restrict__ Wh, unsigned* __restrict__ Wl)
{
    const int idx = blockIdx.x * 256 + threadIdx.x;
    const int kp = idx >> 10, n = idx & 1023;
    const float v0 = W[(size_t)(2 * kp) * DM + n];
    const float v1 = W[(size_t)(2 * kp + 1) * DM + n];
    unsigned hi, lo;
    bsplit2(v0, v1, hi, lo);
    Wh[idx] = hi;  Wl[idx] = lo;
}

__global__ __launch_bounds__(256) void pack_x_kernel(
    const float* __restrict__ X, unsigned* __restrict__ Xh, unsigned* __restrict__ Xl)
{
    __shared__ unsigned smh[32 * 65];
    __shared__ unsigned sml[32 * 65];
    const int tid = threadIdx.x;
    const int m0 = blockIdx.x * 64, kp0 = blockIdx.y * 32;

    #pragma unroll
    for (int it = 0; it < 8; it++) {
        const int idx = it * 256 + tid;
        const int kp_l = idx & 31, m_l = idx >> 5;
        const float2 v = *reinterpret_cast<const float2*>(
            X + (size_t)(m0 + m_l) * DM + 2 * (kp0 + kp_l));
        unsigned hi, lo;
        bsplit2(v.x, v.y, hi, lo);
        smh[kp_l * 65 + m_l] = hi;
        sml[kp_l * 65 + m_l] = lo;
    }
    __syncthreads();
    #pragma unroll
    for (int it = 0; it < 8; it++) {
        const int idx = it * 256 + tid;
        const int kp_l = idx >> 6, m_l = idx & 63;
        Xh[(size_t)(kp0 + kp_l) * M_ROWS + m0 + m_l] = smh[kp_l * 65 + m_l];
        Xl[(size_t)(kp0 + kp_l) * M_ROWS + m0 + m_l] = sml[kp_l * 65 + m_l];
    }
}

// ---------------------------------------------------------------------------
// bf16x2 tensor-core GEMM (unchanged from R5)
// ---------------------------------------------------------------------------
#define SMS 136
#define STAGE_U32 (4 * 8 * SMS)
#define GEMM_SMEM_BYTES (3 * STAGE_U32 * 4)

template <bool HEAD_OUT>
__global__ __launch_bounds__(256) void bf16x2_gemm_kernel(
    const unsigned* __restrict__ Ah, const unsigned* __restrict__ Al,
    const unsigned* __restrict__ Bh, const unsigned* __restrict__ Bl,
    float* __restrict__ C, int M, int N)
{
    extern __shared__ unsigned sm[];

    const int tid  = threadIdx.x;
    const int bRow = blockIdx.y, bCol = blockIdx.x;
    const int wid = tid >> 5, lane = tid & 31;
    const int wm = wid >> 2, wn = wid & 3;
    const int g  = lane >> 2, tg = lane & 3;

    const int lrow = tid >> 5;
    const int lseg = tid & 31;
    const size_t mA = (size_t)bRow * 128 + lseg * 4;
    const size_t nB = (size_t)bCol * 128 + lseg * 4;

    const unsigned dst_base = (unsigned)__cvta_generic_to_shared(sm);
    const unsigned dst_off  = (lrow * SMS + lseg * 4) * 4;

    auto issue = [&](int st, int s) {
        const size_t kpr = (size_t)(s * 8 + lrow);
        const unsigned d0 = dst_base + st * STAGE_U32 * 4 + dst_off;
        CP16(d0,                Ah + kpr * M + mA);
        CP16(d0 + 8 * SMS * 4,  Al + kpr * M + mA);
        CP16(d0 + 16 * SMS * 4, Bh + kpr * N + nB);
        CP16(d0 + 24 * SMS * 4, Bl + kpr * N + nB);
    };

    float acc[4][4][4] = {};

    issue(0, 0); CP_COMMIT();
    issue(1, 1); CP_COMMIT();

    const int NSLAB = 64;
    for (int s = 0; s < NSLAB; s++) {
        CP_WAIT1();
        __syncthreads();
        if (s + 2 < NSLAB) issue((s + 2) % 3, s + 2);
        CP_COMMIT();

        const unsigned* Sb = sm + (s % 3) * STAGE_U32;
        const unsigned* SAh = Sb;
        const unsigned* SAl = Sb + 8 * SMS;
        const unsigned* SBh = Sb + 16 * SMS;
        const unsigned* SBl = Sb + 24 * SMS;

        unsigned a[4][4], bh[4][2], bl[4][2];
        #pragma unroll
        for (int mt = 0; mt < 4; mt++) {
            const int mrow = wm * 64 + mt * 16 + g;
            a[mt][0] = SAh[tg * SMS + mrow];
            a[mt][1] = SAh[tg * SMS + mrow + 8];
            a[mt][2] = SAh[(tg + 4) * SMS + mrow];
            a[mt][3] = SAh[(tg + 4) * SMS + mrow + 8];
        }
        #pragma unroll
        for (int nt = 0; nt < 4; nt++) {
            const int ncol = wn * 32 + nt * 8 + g;
            bh[nt][0] = SBh[tg * SMS + ncol];
            bh[nt][1] = SBh[(tg + 4) * SMS + ncol];
            bl[nt][0] = SBl[tg * SMS + ncol];
            bl[nt][1] = SBl[(tg + 4) * SMS + ncol];
        }
        #pragma unroll
        for (int mt = 0; mt < 4; mt++)
            #pragma unroll
            for (int nt = 0; nt < 4; nt++) mma_bf16(acc[mt][nt], a[mt], bh[nt]);
        #pragma unroll
        for (int mt = 0; mt < 4; mt++)
            #pragma unroll
            for (int nt = 0; nt < 4; nt++) mma_bf16(acc[mt][nt], a[mt], bl[nt]);
        #pragma unroll
        for (int mt = 0; mt < 4; mt++) {
            const int mrow = wm * 64 + mt * 16 + g;
            a[mt][0] = SAl[tg * SMS + mrow];
            a[mt][1] = SAl[tg * SMS + mrow + 8];
            a[mt][2] = SAl[(tg + 4) * SMS + mrow];
            a[mt][3] = SAl[(tg + 4) * SMS + mrow + 8];
        }
        #pragma unroll
        for (int mt = 0; mt < 4; mt++)
            #pragma unroll
            for (int nt = 0; nt < 4; nt++) mma_bf16(acc[mt][nt], a[mt], bh[nt]);
    }

    #pragma unroll
    for (int mt = 0; mt < 4; mt++) {
        #pragma unroll
        for (int nt = 0; nt < 4; nt++) {
            const int n0 = bCol * 128 + wn * 32 + nt * 8 + 2 * tg;
            #pragma unroll
            for (int half = 0; half < 2; half++) {
                const int m = bRow * 128 + wm * 64 + mt * 16 + g + half * 8;
                float2 val = make_float2(acc[mt][nt][half * 2], acc[mt][nt][half * 2 + 1]);
                if (HEAD_OUT) {
                    const int b = m / Tsz, t = m % Tsz;
                    const int h = n0 >> 6, d = n0 & 63;
                    *reinterpret_cast<float2*>(
                        &C[(((size_t)(b * Hn + h)) * Tsz + t) * HDsz + d]) = val;
                } else {
                    *reinterpret_cast<float2*>(&C[(size_t)m * N + n0]) = val;
                }
            }
        }
    }
}

// ---------------------------------------------------------------------------
// featmap via tensor cores: phi = exp(q @ Wf - 0.5||q||^2) * INV_SQRT_NF
// Block: 128 rows x 128 cols, K=64 (32 kp). 4-term bf16 split (hh+hl+lh+ll).
// grid (FROWS/128, 2): y=0 -> q->qp, y=1 -> k->kp.
// ---------------------------------------------------------------------------
#define FMS 136
#define FEAT_SMEM_BYTES ((4 * 32 * FMS + 128) * 4)   // 70,144 B

__global__ __launch_bounds__(256) void featmap_mma_kernel(
    const float* __restrict__ Wf)
{
    extern __shared__ unsigned fsm[];
    unsigned* Ah = fsm;                    // [32][FMS]
    unsigned* Al = Ah + 32 * FMS;
    unsigned* Bh = Al + 32 * FMS;
    unsigned* Bl = Bh + 32 * FMS;
    float*    sqs = (float*)(Bl + 32 * FMS);   // [128]

    const float* in = (blockIdx.y == 0) ? g_q : g_k;
    float* out      = (blockIdx.y == 0) ? g_qp : g_kp;

    const int tid = threadIdx.x;
    const size_t row0 = (size_t)blockIdx.x * 128;

    // ---- load q tile (128 x 64), compute sq, pack A hi/lo ----
    {
        const int m    = tid >> 1;           // 0..127
        const int halfc = (tid & 1) * 32;    // col base 0 or 32
        float vals[32];
        const float* src = in + (row0 + m) * HDsz + halfc;
        #pragma unroll
        for (int i = 0; i < 8; i++) {
            float4 v4 = *reinterpret_cast<const float4*>(src + i * 4);
            vals[i * 4 + 0] = v4.x; vals[i * 4 + 1] = v4.y;
            vals[i * 4 + 2] = v4.z; vals[i * 4 + 3] = v4.w;
        }
        float ss = 0.f;
        #pragma unroll
        for (int i = 0; i < 32; i++) ss += vals[i] * vals[i];
        ss += __shfl_xor_sync(0xffffffffu, ss, 1);
        if ((tid & 1) == 0) sqs[m] = 0.5f * ss;

        const int kp0 = (tid & 1) * 16;
        #pragma unroll
        for (int p = 0; p < 16; p++) {
            unsigned hi, lo;
            bsplit2(vals[2 * p], vals[2 * p + 1], hi, lo);
            Ah[(kp0 + p) * FMS + m] = hi;
            Al[(kp0 + p) * FMS + m] = lo;
        }
    }
    // ---- pack Wf (64 x 128) hi/lo ----
    #pragma unroll
    for (int it = 0; it < 16; it++) {
        const int e = it * 256 + tid;        // over 4096
        const int kp = e >> 7, n = e & 127;
        unsigned hi, lo;
        bsplit2(Wf[(size_t)(2 * kp) * NFsz + n], Wf[(size_t)(2 * kp + 1) * NFsz + n], hi, lo);
        Bh[kp * FMS + n] = hi;
        Bl[kp * FMS + n] = lo;
    }
    __syncthreads();

    // ---- mma: 4 slabs of K=16, 4 terms ----
    const int wid = tid >> 5, lane = tid & 31;
    const int wm = wid >> 2, wn = wid & 3;
    const int g  = lane >> 2, tg = lane & 3;

    float acc[4][4][4] = {};
    #pragma unroll
    for (int s = 0; s < 4; s++) {
        const int k0 = s * 8;
        unsigned a[4][4], bh[4][2], bl[4][2];
        #pragma unroll
        for (int nt = 0; nt < 4; nt++) {
            const int ncol = wn * 32 + nt * 8 + g;
            bh[nt][0] = Bh[(k0 + tg) * FMS + ncol];
            bh[nt][1] = Bh[(k0 + tg + 4) * FMS + ncol];
            bl[nt][0] = Bl[(k0 + tg) * FMS + ncol];
            bl[nt][1] = Bl[(k0 + tg + 4) * FMS + ncol];
        }
        #pragma unroll
        for (int mt = 0; mt < 4; mt++) {
            const int mrow = wm * 64 + mt * 16 + g;
            a[mt][0] = Ah[(k0 + tg) * FMS + mrow];
            a[mt][1] = Ah[(k0 + tg) * FMS + mrow + 8];
            a[mt][2] = Ah[(k0 + tg + 4) * FMS + mrow];
            a[mt][3] = Ah[(k0 + tg + 4) * FMS + mrow + 8];
        }
        #pragma unroll
        for (int mt = 0; mt < 4; mt++)
            #pragma unroll
            for (int nt = 0; nt < 4; nt++) mma_bf16(acc[mt][nt], a[mt], bh[nt]);
        #pragma unroll
        for (int mt = 0; mt < 4; mt++)
            #pragma unroll
            for (int nt = 0; nt < 4; nt++) mma_bf16(acc[mt][nt], a[mt], bl[nt]);
        #pragma unroll
        for (int mt = 0; mt < 4; mt++) {
            const int mrow = wm * 64 + mt * 16 + g;
            a[mt][0] = Al[(k0 + tg) * FMS + mrow];
            a[mt][1] = Al[(k0 + tg) * FMS + mrow + 8];
            a[mt][2] = Al[(k0 + tg + 4) * FMS + mrow];
            a[mt][3] = Al[(k0 + tg + 4) * FMS + mrow + 8];
        }
        #pragma unroll
        for (int mt = 0; mt < 4; mt++)
            #pragma unroll
            for (int nt = 0; nt < 4; nt++) mma_bf16(acc[mt][nt], a[mt], bh[nt]);
        #pragma unroll
        for (int mt = 0; mt < 4; mt++)
            #pragma unroll
            for (int nt = 0; nt < 4; nt++) mma_bf16(acc[mt][nt], a[mt], bl[nt]);
    }

    // ---- epilogue: exp(acc - sq) * scale ----
    #pragma unroll
    for (int mt = 0; mt < 4; mt++) {
        #pragma unroll
        for (int nt = 0; nt < 4; nt++) {
            const int n0 = wn * 32 + nt * 8 + 2 * tg;
            #pragma unroll
            for (int half = 0; half < 2; half++) {
                const int rl = wm * 64 + mt * 16 + g + half * 8;
                const float sq = sqs[rl];
                float2 val;
                val.x = expf(acc[mt][nt][half * 2]     - sq) * INV_SQRT_NF;
                val.y = expf(acc[mt][nt][half * 2 + 1] - sq) * INV_SQRT_NF;
                *reinterpret_cast<float2*>(&out[(row0 + rl) * NFsz + n0]) = val;
            }
        }
    }
}

// ---------------------------------------------------------------------------
// Pass 1: per-chunk state sums (unchanged)
// ---------------------------------------------------------------------------
__global__ __launch_bounds__(256) void chunk_sums_kernel()
{
    __shared__ float kp_s[CH * NFsz];
    __shared__ float v_s [CH * HDsz];
    const int c = blockIdx.x, bh = blockIdx.y;
    const int tid = threadIdx.x;

    const float* kp = g_kp + (size_t)(bh * Tsz + c * CH) * NFsz;
    const float* vv = g_v  + (size_t)(bh * Tsz + c * CH) * HDsz;
    for (int i = tid; i < CH * NFsz; i += 256) kp_s[i] = kp[i];
    for (int i = tid; i < CH * HDsz; i += 256) v_s[i]  = vv[i];
    __syncthreads();

    const int d0 = (tid >> 3) * 4;
    const int e0 = (tid & 7) * 8;
    float acc[4][8] = {};
    for (int i = 0; i < CH; i++) {
        float kk[4], vr[8];
        #pragma unroll
        for (int dd = 0; dd < 4; dd++) kk[dd] = kp_s[i * NFsz + d0 + dd];
        #pragma unroll
        for (int ee = 0; ee < 8; ee++) vr[ee] = v_s[i * HDsz + e0 + ee];
        #pragma unroll
        for (int dd = 0; dd < 4; dd++)
            #pragma unroll
            for (int ee = 0; ee < 8; ee++) acc[dd][ee] += kk[dd] * vr[ee];
    }
    float* Sout = g_S + (size_t)(bh * NCH + c) * NFsz * HDsz;
    #pragma unroll
    for (int dd = 0; dd < 4; dd++)
        #pragma unroll
        for (int ee = 0; ee < 8; ee++)
            Sout[(d0 + dd) * HDsz + e0 + ee] = acc[dd][ee];

    if (tid < NFsz) {
        float s = 0.f;
        for (int i = 0; i < CH; i++) s += kp_s[i * NFsz + tid];
        g_z[(size_t)(bh * NCH + c) * NFsz + tid] = s;
    }
}

// ---------------------------------------------------------------------------
// Pass 2: exclusive prefix (unchanged)
// ---------------------------------------------------------------------------
__global__ __launch_bounds__(256) void prefix_kernel()
{
    const int tid = blockIdx.x * 256 + threadIdx.x;
    const int total = BHn * (NFsz * HDsz + NFsz);
    if (tid >= total) return;
    const int bh = tid / (NFsz * HDsz + NFsz);
    const int r  = tid % (NFsz * HDsz + NFsz);
    float acc = 0.f;
    if (r < NFsz * HDsz) {
        float* p = g_S + (size_t)bh * NCH * NFsz * HDsz + r;
        for (int c = 0; c < NCH; c++) {
            float t = p[(size_t)c * NFsz * HDsz];
            p[(size_t)c * NFsz * HDsz] = acc;
            acc += t;
        }
    } else {
        float* p = g_z + (size_t)bh * NCH * NFsz + (r - NFsz * HDsz);
        for (int c = 0; c < NCH; c++) {
            float t = p[c * NFsz];
            p[c * NFsz] = acc;
            acc += t;
        }
    }
}

// ---------------------------------------------------------------------------
// Pass 3: per-chunk output — now 512 threads (2x warps at forced occ=1)
// ---------------------------------------------------------------------------
__global__ __launch_bounds__(512) void chunk_out_kernel()
{
    extern __shared__ float smf[];
    float* qp_s  = smf;
    float* kp_s  = qp_s + CH * 129;
    float* v_s   = kp_s + CH * 129;
    float* S_s   = v_s  + CH * 65;
    float* A_s   = S_s  + NFsz * 65;
    float* z_s   = A_s  + CH * 65;
    float* den_s = z_s  + NFsz;

    const int c = blockIdx.x, bh = blockIdx.y;
    const int tid = threadIdx.x;

    const float* qp = g_qp + (size_t)(bh * Tsz + c * CH) * NFsz;
    const float* kp = g_kp + (size_t)(bh * Tsz + c * CH) * NFsz;
    const float* vv = g_v  + (size_t)(bh * Tsz + c * CH) * HDsz;
    const float* Sg = g_S  + (size_t)(bh * NCH + c) * NFsz * HDsz;
    const float* zg = g_z  + (size_t)(bh * NCH + c) * NFsz;

    for (int i = tid; i < CH * NFsz; i += 512) {
        const int r = i >> 7, col = i & 127;
        qp_s[r * 129 + col] = qp[i];
        kp_s[r * 129 + col] = kp[i];
    }
    for (int i = tid; i < CH * HDsz; i += 512) {
        const int r = i >> 6, col = i & 63;
        v_s[r * 65 + col] = vv[i];
    }
    for (int i = tid; i < NFsz * HDsz; i += 512) {
        const int r = i >> 6, col = i & 63;
        S_s[r * 65 + col] = Sg[i];
    }
    if (tid < NFsz) z_s[tid] = zg[tid];
    __syncthreads();

    // Phase A: masked A = qp @ kp^T  (thread tile 2x4; 32x16 thread grid)
    {
        const int ti = tid >> 4, tj = tid & 15;
        const int r0 = ti * 2, c0 = tj * 4;
        float acc[2][4] = {};
        for (int d = 0; d < NFsz; d++) {
            float qv[2], kv[4];
            #pragma unroll
            for (int ii = 0; ii < 2; ii++) qv[ii] = qp_s[(r0 + ii) * 129 + d];
            #pragma unroll
            for (int jj = 0; jj < 4; jj++) kv[jj] = kp_s[(c0 + jj) * 129 + d];
            #pragma unroll
            for (int ii = 0; ii < 2; ii++)
                #pragma unroll
                for (int jj = 0; jj < 4; jj++) acc[ii][jj] += qv[ii] * kv[jj];
        }
        #pragma unroll
        for (int ii = 0; ii < 2; ii++)
            #pragma unroll
            for (int jj = 0; jj < 4; jj++) {
                const int i = r0 + ii, j = c0 + jj;
                A_s[i * 65 + j] = (j <= i) ? acc[ii][jj] : 0.f;
            }
    }
    __syncthreads();

    if (tid < CH) {
        float s = EPSv;
        for (int j = 0; j < CH; j++) s += A_s[tid * 65 + j];
        for (int d = 0; d < NFsz; d++) s += qp_s[tid * 129 + d] * z_s[d];
        den_s[tid] = s;
    }
    __syncthreads();

    // Phase B: y = (A @ v + qp @ S_prev) / den  (thread tile 2x4)
    const int ti = tid >> 4, te = tid & 15;
    const int r0 = ti * 2, e0 = te * 4;
    float acc[2][4] = {};
    for (int j = 0; j < CH; j++) {
        float av[2], vr[4];
        #pragma unroll
        for (int ii = 0; ii < 2; ii++) av[ii] = A_s[(r0 + ii) * 65 + j];
        #pragma unroll
        for (int ee = 0; ee < 4; ee++) vr[ee] = v_s[j * 65 + e0 + ee];
        #pragma unroll
        for (int ii = 0; ii < 2; ii++)
            #pragma unroll
            for (int ee = 0; ee < 4; ee++) acc[ii][ee] += av[ii] * vr[ee];
    }
    for (int d = 0; d < NFsz; d++) {
        float qv[2], sv[4];
        #pragma unroll
        for (int ii = 0; ii < 2; ii++) qv[ii] = qp_s[(r0 + ii) * 129 + d];
        #pragma unroll
        for (int ee = 0; ee < 4; ee++) sv[ee] = S_s[d * 65 + e0 + ee];
        #pragma unroll
        for (int ii = 0; ii < 2; ii++)
            #pragma unroll
            for (int ee = 0; ee < 4; ee++) acc[ii][ee] += qv[ii] * sv[ee];
    }

    const int b = bh >> 4, h = bh & 15;
    #pragma unroll
    for (int ii = 0; ii < 2; ii++) {
        const int i = r0 + ii;
        const int t = c * CH + i;
        const float inv_den = 1.0f / den_s[i];
        float4 o;
        o.x = acc[ii][0] * inv_den;
        o.y = acc[ii][1] * inv_den;
        o.z = acc[ii][2] * inv_den;
        o.w = acc[ii][3] * inv_den;
        *reinterpret_cast<float4*>(
            &g_y[((size_t)(b * Tsz + t)) * (Hn * HDsz) + h * HDsz + e0]) = o;
    }
}

// ---------------------------------------------------------------------------
extern "C" void kernel_launch(void* const* d_in, const int* in_sizes, int n_in,
                              void* d_out, int out_size)
{
    const float* x  = (const float*)d_in[0];
    const float* Wq = (const float*)d_in[1];
    const float* Wk = (const float*)d_in[2];
    const float* Wv = (const float*)d_in[3];
    const float* Wo = (const float*)d_in[4];
    const float* Wf = (const float*)d_in[5];
    float* out = (float*)d_out;

    float *q, *k, *v, *y;
    unsigned *Xh, *Xl, *Wh, *Wl;
    cudaGetSymbolAddress((void**)&q,  g_q);
    cudaGetSymbolAddress((void**)&k,  g_k);
    cudaGetSymbolAddress((void**)&v,  g_v);
    cudaGetSymbolAddress((void**)&y,  g_y);
    cudaGetSymbolAddress((void**)&Xh, g_Xh);
    cudaGetSymbolAddress((void**)&Xl, g_Xl);
    cudaGetSymbolAddress((void**)&Wh, g_Wh);
    cudaGetSymbolAddress((void**)&Wl, g_Wl);

    cudaFuncSetAttribute(chunk_out_kernel,
                         cudaFuncAttributeMaxDynamicSharedMemorySize, 136000);
    cudaFuncSetAttribute(bf16x2_gemm_kernel<true>,
                         cudaFuncAttributeMaxDynamicSharedMemorySize, GEMM_SMEM_BYTES);
    cudaFuncSetAttribute(bf16x2_gemm_kernel<false>,
                         cudaFuncAttributeMaxDynamicSharedMemorySize, GEMM_SMEM_BYTES);
    cudaFuncSetAttribute(featmap_mma_kernel,
                         cudaFuncAttributeMaxDynamicSharedMemorySize, FEAT_SMEM_BYTES);

    const int WSTRIDE = KP * DM;
    pack_w_kernel<<<(KP * DM) / 256, 256>>>(Wq, Wh + 0 * WSTRIDE, Wl + 0 * WSTRIDE);
    pack_w_kernel<<<(KP * DM) / 256, 256>>>(Wk, Wh + 1 * WSTRIDE, Wl + 1 * WSTRIDE);
    pack_w_kernel<<<(KP * DM) / 256, 256>>>(Wv, Wh + 2 * WSTRIDE, Wl + 2 * WSTRIDE);
    pack_w_kernel<<<(KP * DM) / 256, 256>>>(Wo, Wh + 3 * WSTRIDE, Wl + 3 * WSTRIDE);
    pack_x_kernel<<<dim3(M_ROWS / 64, KP / 32), 256>>>(x, Xh, Xl);

    const dim3 ggrid(DM / 128, M_ROWS / 128);
    bf16x2_gemm_kernel<true><<<ggrid, 256, GEMM_SMEM_BYTES>>>(
        Xh, Xl, Wh + 0 * WSTRIDE, Wl + 0 * WSTRIDE, q, M_ROWS, DM);
    bf16x2_gemm_kernel<true><<<ggrid, 256, GEMM_SMEM_BYTES>>>(
        Xh, Xl, Wh + 1 * WSTRIDE, Wl + 1 * WSTRIDE, k, M_ROWS, DM);
    bf16x2_gemm_kernel<true><<<ggrid, 256, GEMM_SMEM_BYTES>>>(
        Xh, Xl, Wh + 2 * WSTRIDE, Wl + 2 * WSTRIDE, v, M_ROWS, DM);

    // fused q+k feature maps on tensor cores
    featmap_mma_kernel<<<dim3(FROWS / 128, 2), 256, FEAT_SMEM_BYTES>>>(Wf);

    chunk_sums_kernel<<<dim3(NCH, BHn), 256>>>();
    prefix_kernel<<<2080, 256>>>();
    const size_t smem_bytes = (size_t)(CH * 129 * 2 + CH * 65 + NFsz * 65 + CH * 65 + NFsz + CH) * sizeof(float);
    chunk_out_kernel<<<dim3(NCH, BHn), 512, smem_bytes>>>();

    pack_x_kernel<<<dim3(M_ROWS / 64, KP / 32), 256>>>(y, Xh, Xl);
    bf16x2_gemm_kernel<false><<<ggrid, 256, GEMM_SMEM_BYTES>>>(
        Xh, Xl, Wh + 3 * WSTRIDE, Wl + 3 * WSTRIDE, out, M_ROWS, DM);
}

// round 7
// speedup vs baseline: 2.9989x; 1.5162x over previous
#include <cuda_runtime.h>
#include <cuda_bf16.h>
#include <math.h>

// Problem constants
#define Bsz   4
#define Tsz   2048
#define DM    1024
#define Hn    16
#define HDsz  64
#define NFsz  128
#define CH    64
#define NCH   (Tsz / CH)      // 32
#define BHn   (Bsz * Hn)      // 64
#define EPSv  1e-6f
#define INV_SQRT_NF 0.08838834764831845f

#define M_ROWS (Bsz * Tsz)    // 8192
#define KP     (DM / 2)       // 512
#define FROWS  (BHn * Tsz)    // 131072

// -------------------- scratch (device globals) -----------------------------
__device__ float g_q [BHn * Tsz * HDsz];
__device__ float g_k [BHn * Tsz * HDsz];
__device__ float g_v [BHn * Tsz * HDsz];
__device__ float g_qp[BHn * Tsz * NFsz];
__device__ float g_kp[BHn * Tsz * NFsz];
__device__ float g_S [BHn * NCH * NFsz * HDsz];
__device__ float g_z [BHn * NCH * NFsz];
__device__ float g_y [Bsz * Tsz * Hn * HDsz];

__device__ unsigned g_Xh[KP * M_ROWS];
__device__ unsigned g_Xl[KP * M_ROWS];
__device__ unsigned g_Wh[4 * KP * DM];
__device__ unsigned g_Wl[4 * KP * DM];

// ---------------------------------------------------------------------------
// helpers
// ---------------------------------------------------------------------------
__device__ __forceinline__ void bsplit2(float v0, float v1, unsigned& hi, unsigned& lo) {
    __nv_bfloat16 h0 = __float2bfloat16_rn(v0);
    __nv_bfloat16 h1 = __float2bfloat16_rn(v1);
    float r0 = v0 - __bfloat162float(h0);
    float r1 = v1 - __bfloat162float(h1);
    __nv_bfloat16 l0 = __float2bfloat16_rn(r0);
    __nv_bfloat16 l1 = __float2bfloat16_rn(r1);
    hi = ((unsigned)__bfloat16_as_ushort(h1) << 16) | __bfloat16_as_ushort(h0);
    lo = ((unsigned)__bfloat16_as_ushort(l1) << 16) | __bfloat16_as_ushort(l0);
}

__device__ __forceinline__ float bf_lo(unsigned u) {
    return __bfloat162float(__ushort_as_bfloat16((unsigned short)(u & 0xffffu)));
}
__device__ __forceinline__ float bf_hi(unsigned u) {
    return __bfloat162float(__ushort_as_bfloat16((unsigned short)(u >> 16)));
}

__device__ __forceinline__ void mma_bf16(float c[4], const unsigned a[4], const unsigned b[2]) {
    asm volatile(
        "mma.sync.aligned.m16n8k16.row.col.f32.bf16.bf16.f32 "
        "{%0,%1,%2,%3}, {%4,%5,%6,%7}, {%8,%9}, {%0,%1,%2,%3};"
        : "+f"(c[0]), "+f"(c[1]), "+f"(c[2]), "+f"(c[3])
        : "r"(a[0]), "r"(a[1]), "r"(a[2]), "r"(a[3]), "r"(b[0]), "r"(b[1]));
}

#define CP16(dst, src) \
    asm volatile("cp.async.cg.shared.global [%0], [%1], 16;" :: "r"(dst), "l"(src))
#define CP_COMMIT() asm volatile("cp.async.commit_group;")
#define CP_WAIT1()  asm volatile("cp.async.wait_group 1;")

// ---------------------------------------------------------------------------
// pack_w / pack_x (unchanged)
// ---------------------------------------------------------------------------
__global__ __launch_bounds__(256) void pack_w_kernel(
    const float* __restrict__ W, unsigned* __restrict__ Wh, unsigned* __restrict__ Wl)
{
    const int idx = blockIdx.x * 256 + threadIdx.x;
    const int kp = idx >> 10, n = idx & 1023;
    const float v0 = W[(size_t)(2 * kp) * DM + n];
    const float v1 = W[(size_t)(2 * kp + 1) * DM + n];
    unsigned hi, lo;
    bsplit2(v0, v1, hi, lo);
    Wh[idx] = hi;  Wl[idx] = lo;
}

__global__ __launch_bounds__(256) void pack_x_kernel(
    const float* __restrict__ X, unsigned* __restrict__ Xh, unsigned* __restrict__ Xl)
{
    __shared__ unsigned smh[32 * 65];
    __shared__ unsigned sml[32 * 65];
    const int tid = threadIdx.x;
    const int m0 = blockIdx.x * 64, kp0 = blockIdx.y * 32;

    #pragma unroll
    for (int it = 0; it < 8; it++) {
        const int idx = it * 256 + tid;
        const int kp_l = idx & 31, m_l = idx >> 5;
        const float2 v = *reinterpret_cast<const float2*>(
            X + (size_t)(m0 + m_l) * DM + 2 * (kp0 + kp_l));
        unsigned hi, lo;
        bsplit2(v.x, v.y, hi, lo);
        smh[kp_l * 65 + m_l] = hi;
        sml[kp_l * 65 + m_l] = lo;
    }
    __syncthreads();
    #pragma unroll
    for (int it = 0; it < 8; it++) {
        const int idx = it * 256 + tid;
        const int kp_l = idx >> 6, m_l = idx & 63;
        Xh[(size_t)(kp0 + kp_l) * M_ROWS + m0 + m_l] = smh[kp_l * 65 + m_l];
        Xl[(size_t)(kp0 + kp_l) * M_ROWS + m0 + m_l] = sml[kp_l * 65 + m_l];
    }
}

// ---------------------------------------------------------------------------
// bf16x2 tensor-core GEMM (unchanged from R5)
// ---------------------------------------------------------------------------
#define SMS 136
#define STAGE_U32 (4 * 8 * SMS)
#define GEMM_SMEM_BYTES (3 * STAGE_U32 * 4)

template <bool HEAD_OUT>
__global__ __launch_bounds__(256) void bf16x2_gemm_kernel(
    const unsigned* __restrict__ Ah, const unsigned* __restrict__ Al,
    const unsigned* __restrict__ Bh, const unsigned* __restrict__ Bl,
    float* __restrict__ C, int M, int N)
{
    extern __shared__ unsigned sm[];

    const int tid  = threadIdx.x;
    const int bRow = blockIdx.y, bCol = blockIdx.x;
    const int wid = tid >> 5, lane = tid & 31;
    const int wm = wid >> 2, wn = wid & 3;
    const int g  = lane >> 2, tg = lane & 3;

    const int lrow = tid >> 5;
    const int lseg = tid & 31;
    const size_t mA = (size_t)bRow * 128 + lseg * 4;
    const size_t nB = (size_t)bCol * 128 + lseg * 4;

    const unsigned dst_base = (unsigned)__cvta_generic_to_shared(sm);
    const unsigned dst_off  = (lrow * SMS + lseg * 4) * 4;

    auto issue = [&](int st, int s) {
        const size_t kpr = (size_t)(s * 8 + lrow);
        const unsigned d0 = dst_base + st * STAGE_U32 * 4 + dst_off;
        CP16(d0,                Ah + kpr * M + mA);
        CP16(d0 + 8 * SMS * 4,  Al + kpr * M + mA);
        CP16(d0 + 16 * SMS * 4, Bh + kpr * N + nB);
        CP16(d0 + 24 * SMS * 4, Bl + kpr * N + nB);
    };

    float acc[4][4][4] = {};

    issue(0, 0); CP_COMMIT();
    issue(1, 1); CP_COMMIT();

    const int NSLAB = 64;
    for (int s = 0; s < NSLAB; s++) {
        CP_WAIT1();
        __syncthreads();
        if (s + 2 < NSLAB) issue((s + 2) % 3, s + 2);
        CP_COMMIT();

        const unsigned* Sb = sm + (s % 3) * STAGE_U32;
        const unsigned* SAh = Sb;
        const unsigned* SAl = Sb + 8 * SMS;
        const unsigned* SBh = Sb + 16 * SMS;
        const unsigned* SBl = Sb + 24 * SMS;

        unsigned a[4][4], bh[4][2], bl[4][2];
        #pragma unroll
        for (int mt = 0; mt < 4; mt++) {
            const int mrow = wm * 64 + mt * 16 + g;
            a[mt][0] = SAh[tg * SMS + mrow];
            a[mt][1] = SAh[tg * SMS + mrow + 8];
            a[mt][2] = SAh[(tg + 4) * SMS + mrow];
            a[mt][3] = SAh[(tg + 4) * SMS + mrow + 8];
        }
        #pragma unroll
        for (int nt = 0; nt < 4; nt++) {
            const int ncol = wn * 32 + nt * 8 + g;
            bh[nt][0] = SBh[tg * SMS + ncol];
            bh[nt][1] = SBh[(tg + 4) * SMS + ncol];
            bl[nt][0] = SBl[tg * SMS + ncol];
            bl[nt][1] = SBl[(tg + 4) * SMS + ncol];
        }
        #pragma unroll
        for (int mt = 0; mt < 4; mt++)
            #pragma unroll
            for (int nt = 0; nt < 4; nt++) mma_bf16(acc[mt][nt], a[mt], bh[nt]);
        #pragma unroll
        for (int mt = 0; mt < 4; mt++)
            #pragma unroll
            for (int nt = 0; nt < 4; nt++) mma_bf16(acc[mt][nt], a[mt], bl[nt]);
        #pragma unroll
        for (int mt = 0; mt < 4; mt++) {
            const int mrow = wm * 64 + mt * 16 + g;
            a[mt][0] = SAl[tg * SMS + mrow];
            a[mt][1] = SAl[tg * SMS + mrow + 8];
            a[mt][2] = SAl[(tg + 4) * SMS + mrow];
            a[mt][3] = SAl[(tg + 4) * SMS + mrow + 8];
        }
        #pragma unroll
        for (int mt = 0; mt < 4; mt++)
            #pragma unroll
            for (int nt = 0; nt < 4; nt++) mma_bf16(acc[mt][nt], a[mt], bh[nt]);
    }

    #pragma unroll
    for (int mt = 0; mt < 4; mt++) {
        #pragma unroll
        for (int nt = 0; nt < 4; nt++) {
            const int n0 = bCol * 128 + wn * 32 + nt * 8 + 2 * tg;
            #pragma unroll
            for (int half = 0; half < 2; half++) {
                const int m = bRow * 128 + wm * 64 + mt * 16 + g + half * 8;
                float2 val = make_float2(acc[mt][nt][half * 2], acc[mt][nt][half * 2 + 1]);
                if (HEAD_OUT) {
                    const int b = m / Tsz, t = m % Tsz;
                    const int h = n0 >> 6, d = n0 & 63;
                    *reinterpret_cast<float2*>(
                        &C[(((size_t)(b * Hn + h)) * Tsz + t) * HDsz + d]) = val;
                } else {
                    *reinterpret_cast<float2*>(&C[(size_t)m * N + n0]) = val;
                }
            }
        }
    }
}

// ---------------------------------------------------------------------------
// featmap via tensor cores (unchanged from R6)
// ---------------------------------------------------------------------------
#define FMS 136
#define FEAT_SMEM_BYTES ((4 * 32 * FMS + 128) * 4)

__global__ __launch_bounds__(256) void featmap_mma_kernel(
    const float* __restrict__ Wf)
{
    extern __shared__ unsigned fsm[];
    unsigned* Ah = fsm;
    unsigned* Al = Ah + 32 * FMS;
    unsigned* Bh = Al + 32 * FMS;
    unsigned* Bl = Bh + 32 * FMS;
    float*    sqs = (float*)(Bl + 32 * FMS);

    const float* in = (blockIdx.y == 0) ? g_q : g_k;
    float* out      = (blockIdx.y == 0) ? g_qp : g_kp;

    const int tid = threadIdx.x;
    const size_t row0 = (size_t)blockIdx.x * 128;

    {
        const int m    = tid >> 1;
        const int halfc = (tid & 1) * 32;
        float vals[32];
        const float* src = in + (row0 + m) * HDsz + halfc;
        #pragma unroll
        for (int i = 0; i < 8; i++) {
            float4 v4 = *reinterpret_cast<const float4*>(src + i * 4);
            vals[i * 4 + 0] = v4.x; vals[i * 4 + 1] = v4.y;
            vals[i * 4 + 2] = v4.z; vals[i * 4 + 3] = v4.w;
        }
        float ss = 0.f;
        #pragma unroll
        for (int i = 0; i < 32; i++) ss += vals[i] * vals[i];
        ss += __shfl_xor_sync(0xffffffffu, ss, 1);
        if ((tid & 1) == 0) sqs[m] = 0.5f * ss;

        const int kp0 = (tid & 1) * 16;
        #pragma unroll
        for (int p = 0; p < 16; p++) {
            unsigned hi, lo;
            bsplit2(vals[2 * p], vals[2 * p + 1], hi, lo);
            Ah[(kp0 + p) * FMS + m] = hi;
            Al[(kp0 + p) * FMS + m] = lo;
        }
    }
    #pragma unroll
    for (int it = 0; it < 16; it++) {
        const int e = it * 256 + tid;
        const int kp = e >> 7, n = e & 127;
        unsigned hi, lo;
        bsplit2(Wf[(size_t)(2 * kp) * NFsz + n], Wf[(size_t)(2 * kp + 1) * NFsz + n], hi, lo);
        Bh[kp * FMS + n] = hi;
        Bl[kp * FMS + n] = lo;
    }
    __syncthreads();

    const int wid = tid >> 5, lane = tid & 31;
    const int wm = wid >> 2, wn = wid & 3;
    const int g  = lane >> 2, tg = lane & 3;

    float acc[4][4][4] = {};
    #pragma unroll
    for (int s = 0; s < 4; s++) {
        const int k0 = s * 8;
        unsigned a[4][4], bh[4][2], bl[4][2];
        #pragma unroll
        for (int nt = 0; nt < 4; nt++) {
            const int ncol = wn * 32 + nt * 8 + g;
            bh[nt][0] = Bh[(k0 + tg) * FMS + ncol];
            bh[nt][1] = Bh[(k0 + tg + 4) * FMS + ncol];
            bl[nt][0] = Bl[(k0 + tg) * FMS + ncol];
            bl[nt][1] = Bl[(k0 + tg + 4) * FMS + ncol];
        }
        #pragma unroll
        for (int mt = 0; mt < 4; mt++) {
            const int mrow = wm * 64 + mt * 16 + g;
            a[mt][0] = Ah[(k0 + tg) * FMS + mrow];
            a[mt][1] = Ah[(k0 + tg) * FMS + mrow + 8];
            a[mt][2] = Ah[(k0 + tg + 4) * FMS + mrow];
            a[mt][3] = Ah[(k0 + tg + 4) * FMS + mrow + 8];
        }
        #pragma unroll
        for (int mt = 0; mt < 4; mt++)
            #pragma unroll
            for (int nt = 0; nt < 4; nt++) mma_bf16(acc[mt][nt], a[mt], bh[nt]);
        #pragma unroll
        for (int mt = 0; mt < 4; mt++)
            #pragma unroll
            for (int nt = 0; nt < 4; nt++) mma_bf16(acc[mt][nt], a[mt], bl[nt]);
        #pragma unroll
        for (int mt = 0; mt < 4; mt++) {
            const int mrow = wm * 64 + mt * 16 + g;
            a[mt][0] = Al[(k0 + tg) * FMS + mrow];
            a[mt][1] = Al[(k0 + tg) * FMS + mrow + 8];
            a[mt][2] = Al[(k0 + tg + 4) * FMS + mrow];
            a[mt][3] = Al[(k0 + tg + 4) * FMS + mrow + 8];
        }
        #pragma unroll
        for (int mt = 0; mt < 4; mt++)
            #pragma unroll
            for (int nt = 0; nt < 4; nt++) mma_bf16(acc[mt][nt], a[mt], bh[nt]);
        #pragma unroll
        for (int mt = 0; mt < 4; mt++)
            #pragma unroll
            for (int nt = 0; nt < 4; nt++) mma_bf16(acc[mt][nt], a[mt], bl[nt]);
    }

    #pragma unroll
    for (int mt = 0; mt < 4; mt++) {
        #pragma unroll
        for (int nt = 0; nt < 4; nt++) {
            const int n0 = wn * 32 + nt * 8 + 2 * tg;
            #pragma unroll
            for (int half = 0; half < 2; half++) {
                const int rl = wm * 64 + mt * 16 + g + half * 8;
                const float sq = sqs[rl];
                float2 val;
                val.x = expf(acc[mt][nt][half * 2]     - sq) * INV_SQRT_NF;
                val.y = expf(acc[mt][nt][half * 2 + 1] - sq) * INV_SQRT_NF;
                *reinterpret_cast<float2*>(&out[(row0 + rl) * NFsz + n0]) = val;
            }
        }
    }
}

// ---------------------------------------------------------------------------
// chunk_sums via HMMA: S(128x64) = kp^T @ v, z = colsum(kp).
// Operands packed bf16 hi/lo: KA[p][d] (pairs over chunk pos), VB[p][e].
// grid (NCH, BHn), 256 threads. dyn smem 53.2 KB.
// ---------------------------------------------------------------------------
#define CS_SMEM_U32 (2 * 32 * 136 + 2 * 32 * 72)
#define CS_SMEM_BYTES (CS_SMEM_U32 * 4)

__global__ __launch_bounds__(256) void chunk_sums_mma_kernel()
{
    extern __shared__ unsigned csm[];
    unsigned* KAh = csm;                 // [32][136]
    unsigned* KAl = KAh + 32 * 136;
    unsigned* VBh = KAl + 32 * 136;      // [32][72]
    unsigned* VBl = VBh + 32 * 72;

    const int c = blockIdx.x, bh = blockIdx.y;
    const int tid = threadIdx.x;

    const float* kp = g_kp + (size_t)(bh * Tsz + c * CH) * NFsz;
    const float* vv = g_v  + (size_t)(bh * Tsz + c * CH) * HDsz;

    // pack KA: KA[p][d] = (kp[2p][d], kp[2p+1][d])
    {
        const int d = tid & 127, pg = tid >> 7;   // pg 0..1
        #pragma unroll
        for (int pp = 0; pp < 16; pp++) {
            const int p = pg * 16 + pp;
            const float a = kp[(size_t)(2 * p) * NFsz + d];
            const float b = kp[(size_t)(2 * p + 1) * NFsz + d];
            unsigned hi, lo;
            bsplit2(a, b, hi, lo);
            KAh[p * 136 + d] = hi;
            KAl[p * 136 + d] = lo;
        }
    }
    // pack VB: VB[p][e] = (v[2p][e], v[2p+1][e])
    {
        const int e = tid & 63, pg = tid >> 6;    // pg 0..3
        #pragma unroll
        for (int pp = 0; pp < 8; pp++) {
            const int p = pg * 8 + pp;
            const float a = vv[(size_t)(2 * p) * HDsz + e];
            const float b = vv[(size_t)(2 * p + 1) * HDsz + e];
            unsigned hi, lo;
            bsplit2(a, b, hi, lo);
            VBh[p * 72 + e] = hi;
            VBl[p * 72 + e] = lo;
        }
    }
    // z = colsum(kp) in fp32
    if (tid < NFsz) {
        float s = 0.f;
        for (int i = 0; i < CH; i++) s += kp[(size_t)i * NFsz + tid];
        g_z[(size_t)(bh * NCH + c) * NFsz + tid] = s;
    }
    __syncthreads();

    // mma: M=128 (d), N=64 (e), K=64 (32 pairs, 4 ksteps). warps 4x2.
    const int wid = tid >> 5, lane = tid & 31;
    const int wm = wid >> 1, wn = wid & 1;
    const int g  = lane >> 2, tg = lane & 3;

    float acc[2][4][4] = {};
    #pragma unroll
    for (int ks = 0; ks < 4; ks++) {
        const int k0 = ks * 8;
        unsigned a[2][4], bhf[4][2], blf[4][2];
        #pragma unroll
        for (int mt = 0; mt < 2; mt++) {
            const int mrow = wm * 32 + mt * 16 + g;
            a[mt][0] = KAh[(k0 + tg) * 136 + mrow];
            a[mt][1] = KAh[(k0 + tg) * 136 + mrow + 8];
            a[mt][2] = KAh[(k0 + tg + 4) * 136 + mrow];
            a[mt][3] = KAh[(k0 + tg + 4) * 136 + mrow + 8];
        }
        #pragma unroll
        for (int nt = 0; nt < 4; nt++) {
            const int ncol = wn * 32 + nt * 8 + g;
            bhf[nt][0] = VBh[(k0 + tg) * 72 + ncol];
            bhf[nt][1] = VBh[(k0 + tg + 4) * 72 + ncol];
            blf[nt][0] = VBl[(k0 + tg) * 72 + ncol];
            blf[nt][1] = VBl[(k0 + tg + 4) * 72 + ncol];
        }
        #pragma unroll
        for (int mt = 0; mt < 2; mt++)
            #pragma unroll
            for (int nt = 0; nt < 4; nt++) mma_bf16(acc[mt][nt], a[mt], bhf[nt]);
        #pragma unroll
        for (int mt = 0; mt < 2; mt++)
            #pragma unroll
            for (int nt = 0; nt < 4; nt++) mma_bf16(acc[mt][nt], a[mt], blf[nt]);
        #pragma unroll
        for (int mt = 0; mt < 2; mt++) {
            const int mrow = wm * 32 + mt * 16 + g;
            a[mt][0] = KAl[(k0 + tg) * 136 + mrow];
            a[mt][1] = KAl[(k0 + tg) * 136 + mrow + 8];
            a[mt][2] = KAl[(k0 + tg + 4) * 136 + mrow];
            a[mt][3] = KAl[(k0 + tg + 4) * 136 + mrow + 8];
        }
        #pragma unroll
        for (int mt = 0; mt < 2; mt++)
            #pragma unroll
            for (int nt = 0; nt < 4; nt++) mma_bf16(acc[mt][nt], a[mt], bhf[nt]);
    }

    float* Sout = g_S + (size_t)(bh * NCH + c) * NFsz * HDsz;
    #pragma unroll
    for (int mt = 0; mt < 2; mt++)
        #pragma unroll
        for (int nt = 0; nt < 4; nt++)
            #pragma unroll
            for (int half = 0; half < 2; half++) {
                const int d = wm * 32 + mt * 16 + g + half * 8;
                const int e = wn * 32 + nt * 8 + 2 * tg;
                *reinterpret_cast<float2*>(&Sout[d * HDsz + e]) =
                    make_float2(acc[mt][nt][half * 2], acc[mt][nt][half * 2 + 1]);
            }
}

// ---------------------------------------------------------------------------
// Pass 2: exclusive prefix (unchanged)
// ---------------------------------------------------------------------------
__global__ __launch_bounds__(256) void prefix_kernel()
{
    const int tid = blockIdx.x * 256 + threadIdx.x;
    const int total = BHn * (NFsz * HDsz + NFsz);
    if (tid >= total) return;
    const int bh = tid / (NFsz * HDsz + NFsz);
    const int r  = tid % (NFsz * HDsz + NFsz);
    float acc = 0.f;
    if (r < NFsz * HDsz) {
        float* p = g_S + (size_t)bh * NCH * NFsz * HDsz + r;
        for (int c = 0; c < NCH; c++) {
            float t = p[(size_t)c * NFsz * HDsz];
            p[(size_t)c * NFsz * HDsz] = acc;
            acc += t;
        }
    } else {
        float* p = g_z + (size_t)bh * NCH * NFsz + (r - NFsz * HDsz);
        for (int c = 0; c < NCH; c++) {
            float t = p[c * NFsz];
            p[c * NFsz] = acc;
            acc += t;
        }
    }
}

// ---------------------------------------------------------------------------
// chunk_out via HMMA:
//   A = qp @ kp^T (mask), num = A@v + qp@S_prev, den = rowsum(A)+qp.z+eps
// Operand arrays (u32, [pair][row], stride 72):
//   QA 64p x 64m, KB 64p x 64j, SB 64p x 64e, VB 32p x 64e
//   A_s fp32 (64x66) + AhAl (32p x 64m) aliased over KB after phase A.
// grid (NCH, BHn), 256 threads, dyn smem ~130 KB (occ 1).
// ---------------------------------------------------------------------------
#define CO_QA   0
#define CO_KB   (2 * 64 * 72)              // 9216
#define CO_SB   (CO_KB + 2 * 64 * 72)      // 18432
#define CO_VB   (CO_SB + 2 * 64 * 72)      // 27648
#define CO_ZD   (CO_VB + 2 * 32 * 72)      // 32256
#define CO_SMEM_U32 (CO_ZD + 192)          // 32448
#define CO_SMEM_BYTES (CO_SMEM_U32 * 4)    // 129792
// alias layout inside KB region (9216 u32):
//   A_s fp32 [64][66] = 4224, Ah [32][72] = 2304 at +4224, Al at +6528

__global__ __launch_bounds__(256) void chunk_out_mma_kernel()
{
    extern __shared__ unsigned osm[];
    unsigned* QAh = osm + CO_QA;             // [64][72]
    unsigned* QAl = QAh + 64 * 72;
    unsigned* KBh = osm + CO_KB;             // [64][72]
    unsigned* KBl = KBh + 64 * 72;
    unsigned* SBh = osm + CO_SB;             // [64][72]
    unsigned* SBl = SBh + 64 * 72;
    unsigned* VBh = osm + CO_VB;             // [32][72]
    unsigned* VBl = VBh + 32 * 72;
    float*    z_s   = (float*)(osm + CO_ZD);       // [128]
    float*    den_s = (float*)(osm + CO_ZD + 128); // [64]
    float*    A_s = (float*)(osm + CO_KB);         // alias, [64][66]
    unsigned* Ahp = osm + CO_KB + 4224;            // [32][72]
    unsigned* Alp = Ahp + 32 * 72;

    const int c = blockIdx.x, bh = blockIdx.y;
    const int tid = threadIdx.x;

    const float* qp = g_qp + (size_t)(bh * Tsz + c * CH) * NFsz;
    const float* kp = g_kp + (size_t)(bh * Tsz + c * CH) * NFsz;
    const float* vv = g_v  + (size_t)(bh * Tsz + c * CH) * HDsz;
    const float* Sg = g_S  + (size_t)(bh * NCH + c) * NFsz * HDsz;
    const float* zg = g_z  + (size_t)(bh * NCH + c) * NFsz;

    // ---- pack QA and KB: X[p][m] = (x[m][2p], x[m][2p+1]) ----
    {
        const int m = tid >> 2, qt = tid & 3;     // m 0..63, quarter
        const float* qrow = qp + (size_t)m * NFsz + qt * 32;
        const float* krow = kp + (size_t)m * NFsz + qt * 32;
        #pragma unroll
        for (int i = 0; i < 8; i++) {
            float4 f = *reinterpret_cast<const float4*>(qrow + i * 4);
            const int p = qt * 16 + i * 2;
            unsigned hi, lo;
            bsplit2(f.x, f.y, hi, lo);
            QAh[p * 72 + m] = hi;  QAl[p * 72 + m] = lo;
            bsplit2(f.z, f.w, hi, lo);
            QAh[(p + 1) * 72 + m] = hi;  QAl[(p + 1) * 72 + m] = lo;
        }
        #pragma unroll
        for (int i = 0; i < 8; i++) {
            float4 f = *reinterpret_cast<const float4*>(krow + i * 4);
            const int p = qt * 16 + i * 2;
            unsigned hi, lo;
            bsplit2(f.x, f.y, hi, lo);
            KBh[p * 72 + m] = hi;  KBl[p * 72 + m] = lo;
            bsplit2(f.z, f.w, hi, lo);
            KBh[(p + 1) * 72 + m] = hi;  KBl[(p + 1) * 72 + m] = lo;
        }
    }
    // ---- pack SB: SB[p][e] = (S[2p][e], S[2p+1][e]), p 0..63 ----
    {
        const int e = tid & 63, pg = tid >> 6;   // pg 0..3
        #pragma unroll
        for (int pp = 0; pp < 16; pp++) {
            const int p = pg * 16 + pp;
            const float a = Sg[(size_t)(2 * p) * HDsz + e];
            const float b = Sg[(size_t)(2 * p + 1) * HDsz + e];
            unsigned hi, lo;
            bsplit2(a, b, hi, lo);
            SBh[p * 72 + e] = hi;  SBl[p * 72 + e] = lo;
        }
    }
    // ---- pack VB: VB[p][e] = (v[2p][e], v[2p+1][e]), p 0..31 ----
    {
        const int e = tid & 63, pg = tid >> 6;
        #pragma unroll
        for (int pp = 0; pp < 8; pp++) {
            const int p = pg * 8 + pp;
            const float a = vv[(size_t)(2 * p) * HDsz + e];
            const float b = vv[(size_t)(2 * p + 1) * HDsz + e];
            unsigned hi, lo;
            bsplit2(a, b, hi, lo);
            VBh[p * 72 + e] = hi;  VBl[p * 72 + e] = lo;
        }
    }
    if (tid < NFsz) z_s[tid] = zg[tid];
    __syncthreads();

    const int wid = tid >> 5, lane = tid & 31;
    const int wm = wid >> 2, wn = wid & 3;      // warps 2x4
    const int g  = lane >> 2, tg = lane & 3;

    // ---- Phase A: A = qp @ kp^T  (M=64, N=64, K=128 -> 8 ksteps) ----
    float accA[2][2][4] = {};
    #pragma unroll
    for (int ks = 0; ks < 8; ks++) {
        const int k0 = ks * 8;
        unsigned a[2][4], bhf[2][2], blf[2][2];
        #pragma unroll
        for (int mt = 0; mt < 2; mt++) {
            const int mrow = wm * 32 + mt * 16 + g;
            a[mt][0] = QAh[(k0 + tg) * 72 + mrow];
            a[mt][1] = QAh[(k0 + tg) * 72 + mrow + 8];
            a[mt][2] = QAh[(k0 + tg + 4) * 72 + mrow];
            a[mt][3] = QAh[(k0 + tg + 4) * 72 + mrow + 8];
        }
        #pragma unroll
        for (int nt = 0; nt < 2; nt++) {
            const int ncol = wn * 16 + nt * 8 + g;
            bhf[nt][0] = KBh[(k0 + tg) * 72 + ncol];
            bhf[nt][1] = KBh[(k0 + tg + 4) * 72 + ncol];
            blf[nt][0] = KBl[(k0 + tg) * 72 + ncol];
            blf[nt][1] = KBl[(k0 + tg + 4) * 72 + ncol];
        }
        #pragma unroll
        for (int mt = 0; mt < 2; mt++)
            #pragma unroll
            for (int nt = 0; nt < 2; nt++) mma_bf16(accA[mt][nt], a[mt], bhf[nt]);
        #pragma unroll
        for (int mt = 0; mt < 2; mt++)
            #pragma unroll
            for (int nt = 0; nt < 2; nt++) mma_bf16(accA[mt][nt], a[mt], blf[nt]);
        #pragma unroll
        for (int mt = 0; mt < 2; mt++) {
            const int mrow = wm * 32 + mt * 16 + g;
            a[mt][0] = QAl[(k0 + tg) * 72 + mrow];
            a[mt][1] = QAl[(k0 + tg) * 72 + mrow + 8];
            a[mt][2] = QAl[(k0 + tg + 4) * 72 + mrow];
            a[mt][3] = QAl[(k0 + tg + 4) * 72 + mrow + 8];
        }
        #pragma unroll
        for (int mt = 0; mt < 2; mt++)
            #pragma unroll
            for (int nt = 0; nt < 2; nt++) mma_bf16(accA[mt][nt], a[mt], bhf[nt]);
    }
    __syncthreads();   // all KB reads done; safe to alias

    // ---- write masked A into A_s (aliased over KB) ----
    #pragma unroll
    for (int mt = 0; mt < 2; mt++)
        #pragma unroll
        for (int nt = 0; nt < 2; nt++)
            #pragma unroll
            for (int half = 0; half < 2; half++) {
                const int i = wm * 32 + mt * 16 + g + half * 8;
                const int j0 = wn * 16 + nt * 8 + 2 * tg;
                A_s[i * 66 + j0]     = (j0     <= i) ? accA[mt][nt][half * 2]     : 0.f;
                A_s[i * 66 + j0 + 1] = (j0 + 1 <= i) ? accA[mt][nt][half * 2 + 1] : 0.f;
            }
    __syncthreads();

    // ---- den + pack Ah/Al ----
    if (tid < CH) {
        const int m = tid;
        float s = EPSv;
        for (int j = 0; j < CH; j++) s += A_s[m * 66 + j];
        #pragma unroll 8
        for (int p = 0; p < 64; p++) {
            const unsigned h = QAh[p * 72 + m], l = QAl[p * 72 + m];
            const float v0 = bf_lo(h) + bf_lo(l);
            const float v1 = bf_hi(h) + bf_hi(l);
            s += v0 * z_s[2 * p] + v1 * z_s[2 * p + 1];
        }
        den_s[m] = s;
    }
    {
        const int m = tid >> 2, qt = tid & 3;
        #pragma unroll
        for (int i = 0; i < 8; i++) {
            const int p = qt * 8 + i;
            const float a0 = A_s[m * 66 + 2 * p];
            const float a1 = A_s[m * 66 + 2 * p + 1];
            unsigned hi, lo;
            bsplit2(a0, a1, hi, lo);
            Ahp[p * 72 + m] = hi;  Alp[p * 72 + m] = lo;
        }
    }
    __syncthreads();

    // ---- Phase B: num = A@v (K=64) + qp@S (K=128) ----
    float accB[2][2][4] = {};
    #pragma unroll
    for (int ks = 0; ks < 4; ks++) {
        const int k0 = ks * 8;
        unsigned a[2][4], bhf[2][2], blf[2][2];
        #pragma unroll
        for (int mt = 0; mt < 2; mt++) {
            const int mrow = wm * 32 + mt * 16 + g;
            a[mt][0] = Ahp[(k0 + tg) * 72 + mrow];
            a[mt][1] = Ahp[(k0 + tg) * 72 + mrow + 8];
            a[mt][2] = Ahp[(k0 + tg + 4) * 72 + mrow];
            a[mt][3] = Ahp[(k0 + tg + 4) * 72 + mrow + 8];
        }
        #pragma unroll
        for (int nt = 0; nt < 2; nt++) {
            const int ncol = wn * 16 + nt * 8 + g;
            bhf[nt][0] = VBh[(k0 + tg) * 72 + ncol];
            bhf[nt][1] = VBh[(k0 + tg + 4) * 72 + ncol];
            blf[nt][0] = VBl[(k0 + tg) * 72 + ncol];
            blf[nt][1] = VBl[(k0 + tg + 4) * 72 + ncol];
        }
        #pragma unroll
        for (int mt = 0; mt < 2; mt++)
            #pragma unroll
            for (int nt = 0; nt < 2; nt++) mma_bf16(accB[mt][nt], a[mt], bhf[nt]);
        #pragma unroll
        for (int mt = 0; mt < 2; mt++)
            #pragma unroll
            for (int nt = 0; nt < 2; nt++) mma_bf16(accB[mt][nt], a[mt], blf[nt]);
        #pragma unroll
        for (int mt = 0; mt < 2; mt++) {
            const int mrow = wm * 32 + mt * 16 + g;
            a[mt][0] = Alp[(k0 + tg) * 72 + mrow];
            a[mt][1] = Alp[(k0 + tg) * 72 + mrow + 8];
            a[mt][2] = Alp[(k0 + tg + 4) * 72 + mrow];
            a[mt][3] = Alp[(k0 + tg + 4) * 72 + mrow + 8];
        }
        #pragma unroll
        for (int mt = 0; mt < 2; mt++)
            #pragma unroll
            for (int nt = 0; nt < 2; nt++) mma_bf16(accB[mt][nt], a[mt], bhf[nt]);
    }
    #pragma unroll
    for (int ks = 0; ks < 8; ks++) {
        const int k0 = ks * 8;
        unsigned a[2][4], bhf[2][2], blf[2][2];
        #pragma unroll
        for (int mt = 0; mt < 2; mt++) {
            const int mrow = wm * 32 + mt * 16 + g;
            a[mt][0] = QAh[(k0 + tg) * 72 + mrow];
            a[mt][1] = QAh[(k0 + tg) * 72 + mrow + 8];
            a[mt][2] = QAh[(k0 + tg + 4) * 72 + mrow];
            a[mt][3] = QAh[(k0 + tg + 4) * 72 + mrow + 8];
        }
        #pragma unroll
        for (int nt = 0; nt < 2; nt++) {
            const int ncol = wn * 16 + nt * 8 + g;
            bhf[nt][0] = SBh[(k0 + tg) * 72 + ncol];
            bhf[nt][1] = SBh[(k0 + tg + 4) * 72 + ncol];
            blf[nt][0] = SBl[(k0 + tg) * 72 + ncol];
            blf[nt][1] = SBl[(k0 + tg + 4) * 72 + ncol];
        }
        #pragma unroll
        for (int mt = 0; mt < 2; mt++)
            #pragma unroll
            for (int nt = 0; nt < 2; nt++) mma_bf16(accB[mt][nt], a[mt], bhf[nt]);
        #pragma unroll
        for (int mt = 0; mt < 2; mt++)
            #pragma unroll
            for (int nt = 0; nt < 2; nt++) mma_bf16(accB[mt][nt], a[mt], blf[nt]);
        #pragma unroll
        for (int mt = 0; mt < 2; mt++) {
            const int mrow = wm * 32 + mt * 16 + g;
            a[mt][0] = QAl[(k0 + tg) * 72 + mrow];
            a[mt][1] = QAl[(k0 + tg) * 72 + mrow + 8];
            a[mt][2] = QAl[(k0 + tg + 4) * 72 + mrow];
            a[mt][3] = QAl[(k0 + tg + 4) * 72 + mrow + 8];
        }
        #pragma unroll
        for (int mt = 0; mt < 2; mt++)
            #pragma unroll
            for (int nt = 0; nt < 2; nt++) mma_bf16(accB[mt][nt], a[mt], bhf[nt]);
    }

    // ---- epilogue: y = num / den ----
    const int b = bh >> 4, h = bh & 15;
    #pragma unroll
    for (int mt = 0; mt < 2; mt++)
        #pragma unroll
        for (int nt = 0; nt < 2; nt++)
            #pragma unroll
            for (int half = 0; half < 2; half++) {
                const int i = wm * 32 + mt * 16 + g + half * 8;
                const int e0 = wn * 16 + nt * 8 + 2 * tg;
                const int t = c * CH + i;
                const float inv = 1.0f / den_s[i];
                float2 val = make_float2(accB[mt][nt][half * 2] * inv,
                                         accB[mt][nt][half * 2 + 1] * inv);
                *reinterpret_cast<float2*>(
                    &g_y[((size_t)(b * Tsz + t)) * (Hn * HDsz) + h * HDsz + e0]) = val;
            }
}

// ---------------------------------------------------------------------------
extern "C" void kernel_launch(void* const* d_in, const int* in_sizes, int n_in,
                              void* d_out, int out_size)
{
    const float* x  = (const float*)d_in[0];
    const float* Wq = (const float*)d_in[1];
    const float* Wk = (const float*)d_in[2];
    const float* Wv = (const float*)d_in[3];
    const float* Wo = (const float*)d_in[4];
    const float* Wf = (const float*)d_in[5];
    float* out = (float*)d_out;

    float *q, *k, *v, *y;
    unsigned *Xh, *Xl, *Wh, *Wl;
    cudaGetSymbolAddress((void**)&q,  g_q);
    cudaGetSymbolAddress((void**)&k,  g_k);
    cudaGetSymbolAddress((void**)&v,  g_v);
    cudaGetSymbolAddress((void**)&y,  g_y);
    cudaGetSymbolAddress((void**)&Xh, g_Xh);
    cudaGetSymbolAddress((void**)&Xl, g_Xl);
    cudaGetSymbolAddress((void**)&Wh, g_Wh);
    cudaGetSymbolAddress((void**)&Wl, g_Wl);

    cudaFuncSetAttribute(bf16x2_gemm_kernel<true>,
                         cudaFuncAttributeMaxDynamicSharedMemorySize, GEMM_SMEM_BYTES);
    cudaFuncSetAttribute(bf16x2_gemm_kernel<false>,
                         cudaFuncAttributeMaxDynamicSharedMemorySize, GEMM_SMEM_BYTES);
    cudaFuncSetAttribute(featmap_mma_kernel,
                         cudaFuncAttributeMaxDynamicSharedMemorySize, FEAT_SMEM_BYTES);
    cudaFuncSetAttribute(chunk_sums_mma_kernel,
                         cudaFuncAttributeMaxDynamicSharedMemorySize, CS_SMEM_BYTES);
    cudaFuncSetAttribute(chunk_out_mma_kernel,
                         cudaFuncAttributeMaxDynamicSharedMemorySize, CO_SMEM_BYTES);

    const int WSTRIDE = KP * DM;
    pack_w_kernel<<<(KP * DM) / 256, 256>>>(Wq, Wh + 0 * WSTRIDE, Wl + 0 * WSTRIDE);
    pack_w_kernel<<<(KP * DM) / 256, 256>>>(Wk, Wh + 1 * WSTRIDE, Wl + 1 * WSTRIDE);
    pack_w_kernel<<<(KP * DM) / 256, 256>>>(Wv, Wh + 2 * WSTRIDE, Wl + 2 * WSTRIDE);
    pack_w_kernel<<<(KP * DM) / 256, 256>>>(Wo, Wh + 3 * WSTRIDE, Wl + 3 * WSTRIDE);
    pack_x_kernel<<<dim3(M_ROWS / 64, KP / 32), 256>>>(x, Xh, Xl);

    const dim3 ggrid(DM / 128, M_ROWS / 128);
    bf16x2_gemm_kernel<true><<<ggrid, 256, GEMM_SMEM_BYTES>>>(
        Xh, Xl, Wh + 0 * WSTRIDE, Wl + 0 * WSTRIDE, q, M_ROWS, DM);
    bf16x2_gemm_kernel<true><<<ggrid, 256, GEMM_SMEM_BYTES>>>(
        Xh, Xl, Wh + 1 * WSTRIDE, Wl + 1 * WSTRIDE, k, M_ROWS, DM);
    bf16x2_gemm_kernel<true><<<ggrid, 256, GEMM_SMEM_BYTES>>>(
        Xh, Xl, Wh + 2 * WSTRIDE, Wl + 2 * WSTRIDE, v, M_ROWS, DM);

    featmap_mma_kernel<<<dim3(FROWS / 128, 2), 256, FEAT_SMEM_BYTES>>>(Wf);

    chunk_sums_mma_kernel<<<dim3(NCH, BHn), 256, CS_SMEM_BYTES>>>();
    prefix_kernel<<<2080, 256>>>();
    chunk_out_mma_kernel<<<dim3(NCH, BHn), 256, CO_SMEM_BYTES>>>();

    pack_x_kernel<<<dim3(M_ROWS / 64, KP / 32), 256>>>(y, Xh, Xl);
    bf16x2_gemm_kernel<false><<<ggrid, 256, GEMM_SMEM_BYTES>>>(
        Xh, Xl, Wh + 3 * WSTRIDE, Wl + 3 * WSTRIDE, out, M_ROWS, DM);
}

// round 13
// speedup vs baseline: 3.2919x; 1.0977x over previous
#include <cuda_runtime.h>
#include <cuda_bf16.h>
#include <stdint.h>
#include <math.h>

// Problem constants
#define Bsz   4
#define Tsz   2048
#define DM    1024
#define Hn    16
#define HDsz  64
#define NFsz  128
#define CH    64
#define NCH   (Tsz / CH)      // 32
#define BHn   (Bsz * Hn)      // 64
#define EPSv  1e-6f
#define INV_SQRT_NF 0.08838834764831845f

#define M_ROWS (Bsz * Tsz)    // 8192
#define KP     (DM / 2)       // 512
#define FROWS  (BHn * Tsz)    // 131072

// -------------------- scratch (device globals) -----------------------------
__device__ float g_q [BHn * Tsz * HDsz];
__device__ float g_k [BHn * Tsz * HDsz];
__device__ float g_v [BHn * Tsz * HDsz];
__device__ float g_qp[BHn * Tsz * NFsz];
__device__ float g_kp[BHn * Tsz * NFsz];
__device__ float g_S [BHn * NCH * NFsz * HDsz];
__device__ float g_z [BHn * NCH * NFsz];
__device__ float g_y [Bsz * Tsz * Hn * HDsz];

__device__ unsigned g_Xh[KP * M_ROWS];
__device__ unsigned g_Xl[KP * M_ROWS];
__device__ unsigned g_Wh[4 * KP * DM];
__device__ unsigned g_Wl[4 * KP * DM];

// ---------------------------------------------------------------------------
// helpers
// ---------------------------------------------------------------------------
__device__ __forceinline__ void bsplit2(float v0, float v1, unsigned& hi, unsigned& lo) {
    __nv_bfloat16 h0 = __float2bfloat16_rn(v0);
    __nv_bfloat16 h1 = __float2bfloat16_rn(v1);
    float r0 = v0 - __bfloat162float(h0);
    float r1 = v1 - __bfloat162float(h1);
    __nv_bfloat16 l0 = __float2bfloat16_rn(r0);
    __nv_bfloat16 l1 = __float2bfloat16_rn(r1);
    hi = ((unsigned)__bfloat16_as_ushort(h1) << 16) | __bfloat16_as_ushort(h0);
    lo = ((unsigned)__bfloat16_as_ushort(l1) << 16) | __bfloat16_as_ushort(l0);
}

__device__ __forceinline__ float bf_lo(unsigned u) {
    return __bfloat162float(__ushort_as_bfloat16((unsigned short)(u & 0xffffu)));
}
__device__ __forceinline__ float bf_hi(unsigned u) {
    return __bfloat162float(__ushort_as_bfloat16((unsigned short)(u >> 16)));
}

__device__ __forceinline__ void mma_bf16(float c[4], const unsigned a[4], const unsigned b[2]) {
    asm volatile(
        "mma.sync.aligned.m16n8k16.row.col.f32.bf16.bf16.f32 "
        "{%0,%1,%2,%3}, {%4,%5,%6,%7}, {%8,%9}, {%0,%1,%2,%3};"
        : "+f"(c[0]), "+f"(c[1]), "+f"(c[2]), "+f"(c[3])
        : "r"(a[0]), "r"(a[1]), "r"(a[2]), "r"(a[3]), "r"(b[0]), "r"(b[1]));
}

#define CP16(dst, src) \
    asm volatile("cp.async.cg.shared.global [%0], [%1], 16;" :: "r"(dst), "l"(src))
#define CP_COMMIT() asm volatile("cp.async.commit_group;")
#define CP_WAIT1()  asm volatile("cp.async.wait_group 1;")

// ---------------------------------------------------------------------------
// pack_w / pack_x
// ---------------------------------------------------------------------------
__global__ __launch_bounds__(256) void pack_w_kernel(
    const float* __restrict__ W, unsigned* __restrict__ Wh, unsigned* __restrict__ Wl)
{
    const int idx = blockIdx.x * 256 + threadIdx.x;
    const int kp = idx >> 10, n = idx & 1023;
    const float v0 = W[(size_t)(2 * kp) * DM + n];
    const float v1 = W[(size_t)(2 * kp + 1) * DM + n];
    unsigned hi, lo;
    bsplit2(v0, v1, hi, lo);
    Wh[idx] = hi;  Wl[idx] = lo;
}

__global__ __launch_bounds__(256) void pack_x_kernel(
    const float* __restrict__ X, unsigned* __restrict__ Xh, unsigned* __restrict__ Xl)
{
    __shared__ unsigned smh[32 * 65];
    __shared__ unsigned sml[32 * 65];
    const int tid = threadIdx.x;
    const int m0 = blockIdx.x * 64, kp0 = blockIdx.y * 32;

    #pragma unroll
    for (int it = 0; it < 8; it++) {
        const int idx = it * 256 + tid;
        const int kp_l = idx & 31, m_l = idx >> 5;
        const float2 v = *reinterpret_cast<const float2*>(
            X + (size_t)(m0 + m_l) * DM + 2 * (kp0 + kp_l));
        unsigned hi, lo;
        bsplit2(v.x, v.y, hi, lo);
        smh[kp_l * 65 + m_l] = hi;
        sml[kp_l * 65 + m_l] = lo;
    }
    __syncthreads();
    #pragma unroll
    for (int it = 0; it < 8; it++) {
        const int idx = it * 256 + tid;
        const int kp_l = idx >> 6, m_l = idx & 63;
        Xh[(size_t)(kp0 + kp_l) * M_ROWS + m0 + m_l] = smh[kp_l * 65 + m_l];
        Xl[(size_t)(kp0 + kp_l) * M_ROWS + m0 + m_l] = sml[kp_l * 65 + m_l];
    }
}

// ---------------------------------------------------------------------------
// bf16x2 tensor-core GEMM. __launch_bounds__(256,2) caps regs at 128 so two
// CTAs co-reside per SM (3-stage smem 52KB x2 = 104KB fits) and hide the
// per-slab sync/wait bubbles. blockIdx.x>>3 selects {weight, output} so QKV
// runs as ONE launch, grid (24, 64). Out-proj: grid (8, 64), which==0.
// ---------------------------------------------------------------------------
#define SMS 136
#define STAGE_U32 (4 * 8 * SMS)
#define GEMM_SMEM_BYTES (3 * STAGE_U32 * 4)

template <bool HEAD_OUT>
__global__ __launch_bounds__(256, 2) void bf16x2_gemm_kernel(
    const unsigned* __restrict__ Ah, const unsigned* __restrict__ Al,
    const unsigned* __restrict__ Bh_base, const unsigned* __restrict__ Bl_base,
    float* __restrict__ C0, float* __restrict__ C1, float* __restrict__ C2,
    int M, int N)
{
    extern __shared__ unsigned sm[];

    const int tid  = threadIdx.x;
    const int bRow = blockIdx.y;
    const int which = blockIdx.x >> 3;
    const int bCol = blockIdx.x & 7;
    const unsigned* Bh = Bh_base + (size_t)which * KP * DM;
    const unsigned* Bl = Bl_base + (size_t)which * KP * DM;
    float* C = (which == 0) ? C0 : ((which == 1) ? C1 : C2);

    const int wid = tid >> 5, lane = tid & 31;
    const int wm = wid >> 2, wn = wid & 3;
    const int g  = lane >> 2, tg = lane & 3;

    const int lrow = tid >> 5;
    const int lseg = tid & 31;
    const size_t mA = (size_t)bRow * 128 + lseg * 4;
    const size_t nB = (size_t)bCol * 128 + lseg * 4;

    const unsigned dst_base = (unsigned)__cvta_generic_to_shared(sm);
    const unsigned dst_off  = (lrow * SMS + lseg * 4) * 4;

    auto issue = [&](int st, int s) {
        const size_t kpr = (size_t)(s * 8 + lrow);
        const unsigned d0 = dst_base + st * STAGE_U32 * 4 + dst_off;
        CP16(d0,                Ah + kpr * M + mA);
        CP16(d0 + 8 * SMS * 4,  Al + kpr * M + mA);
        CP16(d0 + 16 * SMS * 4, Bh + kpr * N + nB);
        CP16(d0 + 24 * SMS * 4, Bl + kpr * N + nB);
    };

    float acc[4][4][4] = {};

    issue(0, 0); CP_COMMIT();
    issue(1, 1); CP_COMMIT();

    const int NSLAB = 64;
    for (int s = 0; s < NSLAB; s++) {
        CP_WAIT1();
        __syncthreads();
        if (s + 2 < NSLAB) issue((s + 2) % 3, s + 2);
        CP_COMMIT();

        const unsigned* Sb = sm + (s % 3) * STAGE_U32;
        const unsigned* SAh = Sb;
        const unsigned* SAl = Sb + 8 * SMS;
        const unsigned* SBh = Sb + 16 * SMS;
        const unsigned* SBl = Sb + 24 * SMS;

        unsigned a[4][4], bh[4][2], bl[4][2];
        #pragma unroll
        for (int mt = 0; mt < 4; mt++) {
            const int mrow = wm * 64 + mt * 16 + g;
            a[mt][0] = SAh[tg * SMS + mrow];
            a[mt][1] = SAh[tg * SMS + mrow + 8];
            a[mt][2] = SAh[(tg + 4) * SMS + mrow];
            a[mt][3] = SAh[(tg + 4) * SMS + mrow + 8];
        }
        #pragma unroll
        for (int nt = 0; nt < 4; nt++) {
            const int ncol = wn * 32 + nt * 8 + g;
            bh[nt][0] = SBh[tg * SMS + ncol];
            bh[nt][1] = SBh[(tg + 4) * SMS + ncol];
            bl[nt][0] = SBl[tg * SMS + ncol];
            bl[nt][1] = SBl[(tg + 4) * SMS + ncol];
        }
        #pragma unroll
        for (int mt = 0; mt < 4; mt++)
            #pragma unroll
            for (int nt = 0; nt < 4; nt++) mma_bf16(acc[mt][nt], a[mt], bh[nt]);
        #pragma unroll
        for (int mt = 0; mt < 4; mt++)
            #pragma unroll
            for (int nt = 0; nt < 4; nt++) mma_bf16(acc[mt][nt], a[mt], bl[nt]);
        #pragma unroll
        for (int mt = 0; mt < 4; mt++) {
            const int mrow = wm * 64 + mt * 16 + g;
            a[mt][0] = SAl[tg * SMS + mrow];
            a[mt][1] = SAl[tg * SMS + mrow + 8];
            a[mt][2] = SAl[(tg + 4) * SMS + mrow];
            a[mt][3] = SAl[(tg + 4) * SMS + mrow + 8];
        }
        #pragma unroll
        for (int mt = 0; mt < 4; mt++)
            #pragma unroll
            for (int nt = 0; nt < 4; nt++) mma_bf16(acc[mt][nt], a[mt], bh[nt]);
    }

    #pragma unroll
    for (int mt = 0; mt < 4; mt++) {
        #pragma unroll
        for (int nt = 0; nt < 4; nt++) {
            const int n0 = bCol * 128 + wn * 32 + nt * 8 + 2 * tg;
            #pragma unroll
            for (int half = 0; half < 2; half++) {
                const int m = bRow * 128 + wm * 64 + mt * 16 + g + half * 8;
                float2 val = make_float2(acc[mt][nt][half * 2], acc[mt][nt][half * 2 + 1]);
                if (HEAD_OUT) {
                    const int b = m / Tsz, t = m % Tsz;
                    const int h = n0 >> 6, d = n0 & 63;
                    *reinterpret_cast<float2*>(
                        &C[(((size_t)(b * Hn + h)) * Tsz + t) * HDsz + d]) = val;
                } else {
                    *reinterpret_cast<float2*>(&C[(size_t)m * N + n0]) = val;
                }
            }
        }
    }
}

// ---------------------------------------------------------------------------
// featmap via tensor cores
// ---------------------------------------------------------------------------
#define FMS 136
#define FEAT_SMEM_BYTES ((4 * 32 * FMS + 128) * 4)

__global__ __launch_bounds__(256) void featmap_mma_kernel(
    const float* __restrict__ Wf)
{
    extern __shared__ unsigned fsm[];
    unsigned* Ah = fsm;
    unsigned* Al = Ah + 32 * FMS;
    unsigned* Bh = Al + 32 * FMS;
    unsigned* Bl = Bh + 32 * FMS;
    float*    sqs = (float*)(Bl + 32 * FMS);

    const float* in = (blockIdx.y == 0) ? g_q : g_k;
    float* out      = (blockIdx.y == 0) ? g_qp : g_kp;

    const int tid = threadIdx.x;
    const size_t row0 = (size_t)blockIdx.x * 128;

    {
        const int m    = tid >> 1;
        const int halfc = (tid & 1) * 32;
        float vals[32];
        const float* src = in + (row0 + m) * HDsz + halfc;
        #pragma unroll
        for (int i = 0; i < 8; i++) {
            float4 v4 = *reinterpret_cast<const float4*>(src + i * 4);
            vals[i * 4 + 0] = v4.x; vals[i * 4 + 1] = v4.y;
            vals[i * 4 + 2] = v4.z; vals[i * 4 + 3] = v4.w;
        }
        float ss = 0.f;
        #pragma unroll
        for (int i = 0; i < 32; i++) ss += vals[i] * vals[i];
        ss += __shfl_xor_sync(0xffffffffu, ss, 1);
        if ((tid & 1) == 0) sqs[m] = 0.5f * ss;

        const int kp0 = (tid & 1) * 16;
        #pragma unroll
        for (int p = 0; p < 16; p++) {
            unsigned hi, lo;
            bsplit2(vals[2 * p], vals[2 * p + 1], hi, lo);
            Ah[(kp0 + p) * FMS + m] = hi;
            Al[(kp0 + p) * FMS + m] = lo;
        }
    }
    #pragma unroll
    for (int it = 0; it < 16; it++) {
        const int e = it * 256 + tid;
        const int kp = e >> 7, n = e & 127;
        unsigned hi, lo;
        bsplit2(Wf[(size_t)(2 * kp) * NFsz + n], Wf[(size_t)(2 * kp + 1) * NFsz + n], hi, lo);
        Bh[kp * FMS + n] = hi;
        Bl[kp * FMS + n] = lo;
    }
    __syncthreads();

    const int wid = tid >> 5, lane = tid & 31;
    const int wm = wid >> 2, wn = wid & 3;
    const int g  = lane >> 2, tg = lane & 3;

    float acc[4][4][4] = {};
    #pragma unroll
    for (int s = 0; s < 4; s++) {
        const int k0 = s * 8;
        unsigned a[4][4], bh[4][2], bl[4][2];
        #pragma unroll
        for (int nt = 0; nt < 4; nt++) {
            const int ncol = wn * 32 + nt * 8 + g;
            bh[nt][0] = Bh[(k0 + tg) * FMS + ncol];
            bh[nt][1] = Bh[(k0 + tg + 4) * FMS + ncol];
            bl[nt][0] = Bl[(k0 + tg) * FMS + ncol];
            bl[nt][1] = Bl[(k0 + tg + 4) * FMS + ncol];
        }
        #pragma unroll
        for (int mt = 0; mt < 4; mt++) {
            const int mrow = wm * 64 + mt * 16 + g;
            a[mt][0] = Ah[(k0 + tg) * FMS + mrow];
            a[mt][1] = Ah[(k0 + tg) * FMS + mrow + 8];
            a[mt][2] = Ah[(k0 + tg + 4) * FMS + mrow];
            a[mt][3] = Ah[(k0 + tg + 4) * FMS + mrow + 8];
        }
        #pragma unroll
        for (int mt = 0; mt < 4; mt++)
            #pragma unroll
            for (int nt = 0; nt < 4; nt++) mma_bf16(acc[mt][nt], a[mt], bh[nt]);
        #pragma unroll
        for (int mt = 0; mt < 4; mt++)
            #pragma unroll
            for (int nt = 0; nt < 4; nt++) mma_bf16(acc[mt][nt], a[mt], bl[nt]);
        #pragma unroll
        for (int mt = 0; mt < 4; mt++) {
            const int mrow = wm * 64 + mt * 16 + g;
            a[mt][0] = Al[(k0 + tg) * FMS + mrow];
            a[mt][1] = Al[(k0 + tg) * FMS + mrow + 8];
            a[mt][2] = Al[(k0 + tg + 4) * FMS + mrow];
            a[mt][3] = Al[(k0 + tg + 4) * FMS + mrow + 8];
        }
        #pragma unroll
        for (int mt = 0; mt < 4; mt++)
            #pragma unroll
            for (int nt = 0; nt < 4; nt++) mma_bf16(acc[mt][nt], a[mt], bh[nt]);
        #pragma unroll
        for (int mt = 0; mt < 4; mt++)
            #pragma unroll
            for (int nt = 0; nt < 4; nt++) mma_bf16(acc[mt][nt], a[mt], bl[nt]);
    }

    #pragma unroll
    for (int mt = 0; mt < 4; mt++) {
        #pragma unroll
        for (int nt = 0; nt < 4; nt++) {
            const int n0 = wn * 32 + nt * 8 + 2 * tg;
            #pragma unroll
            for (int half = 0; half < 2; half++) {
                const int rl = wm * 64 + mt * 16 + g + half * 8;
                const float sq = sqs[rl];
                float2 val;
                val.x = expf(acc[mt][nt][half * 2]     - sq) * INV_SQRT_NF;
                val.y = expf(acc[mt][nt][half * 2 + 1] - sq) * INV_SQRT_NF;
                *reinterpret_cast<float2*>(&out[(row0 + rl) * NFsz + n0]) = val;
            }
        }
    }
}

// ---------------------------------------------------------------------------
// chunk_sums via HMMA
// ---------------------------------------------------------------------------
#define CS_SMEM_U32 (2 * 32 * 136 + 2 * 32 * 72)
#define CS_SMEM_BYTES (CS_SMEM_U32 * 4)

__global__ __launch_bounds__(256) void chunk_sums_mma_kernel()
{
    extern __shared__ unsigned csm[];
    unsigned* KAh = csm;
    unsigned* KAl = KAh + 32 * 136;
    unsigned* VBh = KAl + 32 * 136;
    unsigned* VBl = VBh + 32 * 72;

    const int c = blockIdx.x, bh = blockIdx.y;
    const int tid = threadIdx.x;

    const float* kp = g_kp + (size_t)(bh * Tsz + c * CH) * NFsz;
    const float* vv = g_v  + (size_t)(bh * Tsz + c * CH) * HDsz;

    {
        const int d = tid & 127, pg = tid >> 7;
        #pragma unroll
        for (int pp = 0; pp < 16; pp++) {
            const int p = pg * 16 + pp;
            const float a = kp[(size_t)(2 * p) * NFsz + d];
            const float b = kp[(size_t)(2 * p + 1) * NFsz + d];
            unsigned hi, lo;
            bsplit2(a, b, hi, lo);
            KAh[p * 136 + d] = hi;
            KAl[p * 136 + d] = lo;
        }
    }
    {
        const int e = tid & 63, pg = tid >> 6;
        #pragma unroll
        for (int pp = 0; pp < 8; pp++) {
            const int p = pg * 8 + pp;
            const float a = vv[(size_t)(2 * p) * HDsz + e];
            const float b = vv[(size_t)(2 * p + 1) * HDsz + e];
            unsigned hi, lo;
            bsplit2(a, b, hi, lo);
            VBh[p * 72 + e] = hi;
            VBl[p * 72 + e] = lo;
        }
    }
    if (tid < NFsz) {
        float s = 0.f;
        for (int i = 0; i < CH; i++) s += kp[(size_t)i * NFsz + tid];
        g_z[(size_t)(bh * NCH + c) * NFsz + tid] = s;
    }
    __syncthreads();

    const int wid = tid >> 5, lane = tid & 31;
    const int wm = wid >> 1, wn = wid & 1;
    const int g  = lane >> 2, tg = lane & 3;

    float acc[2][4][4] = {};
    #pragma unroll
    for (int ks = 0; ks < 4; ks++) {
        const int k0 = ks * 8;
        unsigned a[2][4], bhf[4][2], blf[4][2];
        #pragma unroll
        for (int mt = 0; mt < 2; mt++) {
            const int mrow = wm * 32 + mt * 16 + g;
            a[mt][0] = KAh[(k0 + tg) * 136 + mrow];
            a[mt][1] = KAh[(k0 + tg) * 136 + mrow + 8];
            a[mt][2] = KAh[(k0 + tg + 4) * 136 + mrow];
            a[mt][3] = KAh[(k0 + tg + 4) * 136 + mrow + 8];
        }
        #pragma unroll
        for (int nt = 0; nt < 4; nt++) {
            const int ncol = wn * 32 + nt * 8 + g;
            bhf[nt][0] = VBh[(k0 + tg) * 72 + ncol];
            bhf[nt][1] = VBh[(k0 + tg + 4) * 72 + ncol];
            blf[nt][0] = VBl[(k0 + tg) * 72 + ncol];
            blf[nt][1] = VBl[(k0 + tg + 4) * 72 + ncol];
        }
        #pragma unroll
        for (int mt = 0; mt < 2; mt++)
            #pragma unroll
            for (int nt = 0; nt < 4; nt++) mma_bf16(acc[mt][nt], a[mt], bhf[nt]);
        #pragma unroll
        for (int mt = 0; mt < 2; mt++)
            #pragma unroll
            for (int nt = 0; nt < 4; nt++) mma_bf16(acc[mt][nt], a[mt], blf[nt]);
        #pragma unroll
        for (int mt = 0; mt < 2; mt++) {
            const int mrow = wm * 32 + mt * 16 + g;
            a[mt][0] = KAl[(k0 + tg) * 136 + mrow];
            a[mt][1] = KAl[(k0 + tg) * 136 + mrow + 8];
            a[mt][2] = KAl[(k0 + tg + 4) * 136 + mrow];
            a[mt][3] = KAl[(k0 + tg + 4) * 136 + mrow + 8];
        }
        #pragma unroll
        for (int mt = 0; mt < 2; mt++)
            #pragma unroll
            for (int nt = 0; nt < 4; nt++) mma_bf16(acc[mt][nt], a[mt], bhf[nt]);
    }

    float* Sout = g_S + (size_t)(bh * NCH + c) * NFsz * HDsz;
    #pragma unroll
    for (int mt = 0; mt < 2; mt++)
        #pragma unroll
        for (int nt = 0; nt < 4; nt++)
            #pragma unroll
            for (int half = 0; half < 2; half++) {
                const int d = wm * 32 + mt * 16 + g + half * 8;
                const int e = wn * 32 + nt * 8 + 2 * tg;
                *reinterpret_cast<float2*>(&Sout[d * HDsz + e]) =
                    make_float2(acc[mt][nt][half * 2], acc[mt][nt][half * 2 + 1]);
            }
}

// ---------------------------------------------------------------------------
// Pass 2: exclusive prefix
// ---------------------------------------------------------------------------
__global__ __launch_bounds__(256) void prefix_kernel()
{
    const int tid = blockIdx.x * 256 + threadIdx.x;
    const int total = BHn * (NFsz * HDsz + NFsz);
    if (tid >= total) return;
    const int bh = tid / (NFsz * HDsz + NFsz);
    const int r  = tid % (NFsz * HDsz + NFsz);
    float acc = 0.f;
    if (r < NFsz * HDsz) {
        float* p = g_S + (size_t)bh * NCH * NFsz * HDsz + r;
        for (int c = 0; c < NCH; c++) {
            float t = p[(size_t)c * NFsz * HDsz];
            p[(size_t)c * NFsz * HDsz] = acc;
            acc += t;
        }
    } else {
        float* p = g_z + (size_t)bh * NCH * NFsz + (r - NFsz * HDsz);
        for (int c = 0; c < NCH; c++) {
            float t = p[c * NFsz];
            p[c * NFsz] = acc;
            acc += t;
        }
    }
}

// ---------------------------------------------------------------------------
// chunk_out via HMMA
// ---------------------------------------------------------------------------
#define CO_QA   0
#define CO_KB   (2 * 64 * 72)
#define CO_SB   (CO_KB + 2 * 64 * 72)
#define CO_VB   (CO_SB + 2 * 64 * 72)
#define CO_ZD   (CO_VB + 2 * 32 * 72)
#define CO_SMEM_U32 (CO_ZD + 192)
#define CO_SMEM_BYTES (CO_SMEM_U32 * 4)

__global__ __launch_bounds__(256) void chunk_out_mma_kernel()
{
    extern __shared__ unsigned osm[];
    unsigned* QAh = osm + CO_QA;
    unsigned* QAl = QAh + 64 * 72;
    unsigned* KBh = osm + CO_KB;
    unsigned* KBl = KBh + 64 * 72;
    unsigned* SBh = osm + CO_SB;
    unsigned* SBl = SBh + 64 * 72;
    unsigned* VBh = osm + CO_VB;
    unsigned* VBl = VBh + 32 * 72;
    float*    z_s   = (float*)(osm + CO_ZD);
    float*    den_s = (float*)(osm + CO_ZD + 128);
    float*    A_s = (float*)(osm + CO_KB);
    unsigned* Ahp = osm + CO_KB + 4224;
    unsigned* Alp = Ahp + 32 * 72;

    const int c = blockIdx.x, bh = blockIdx.y;
    const int tid = threadIdx.x;

    const float* qp = g_qp + (size_t)(bh * Tsz + c * CH) * NFsz;
    const float* kp = g_kp + (size_t)(bh * Tsz + c * CH) * NFsz;
    const float* vv = g_v  + (size_t)(bh * Tsz + c * CH) * HDsz;
    const float* Sg = g_S  + (size_t)(bh * NCH + c) * NFsz * HDsz;
    const float* zg = g_z  + (size_t)(bh * NCH + c) * NFsz;

    {
        const int m = tid >> 2, qt = tid & 3;
        const float* qrow = qp + (size_t)m * NFsz + qt * 32;
        const float* krow = kp + (size_t)m * NFsz + qt * 32;
        #pragma unroll
        for (int i = 0; i < 8; i++) {
            float4 f = *reinterpret_cast<const float4*>(qrow + i * 4);
            const int p = qt * 16 + i * 2;
            unsigned hi, lo;
            bsplit2(f.x, f.y, hi, lo);
            QAh[p * 72 + m] = hi;  QAl[p * 72 + m] = lo;
            bsplit2(f.z, f.w, hi, lo);
            QAh[(p + 1) * 72 + m] = hi;  QAl[(p + 1) * 72 + m] = lo;
        }
        #pragma unroll
        for (int i = 0; i < 8; i++) {
            float4 f = *reinterpret_cast<const float4*>(krow + i * 4);
            const int p = qt * 16 + i * 2;
            unsigned hi, lo;
            bsplit2(f.x, f.y, hi, lo);
            KBh[p * 72 + m] = hi;  KBl[p * 72 + m] = lo;
            bsplit2(f.z, f.w, hi, lo);
            KBh[(p + 1) * 72 + m] = hi;  KBl[(p + 1) * 72 + m] = lo;
        }
    }
    {
        const int e = tid & 63, pg = tid >> 6;
        #pragma unroll
        for (int pp = 0; pp < 16; pp++) {
            const int p = pg * 16 + pp;
            const float a = Sg[(size_t)(2 * p) * HDsz + e];
            const float b = Sg[(size_t)(2 * p + 1) * HDsz + e];
            unsigned hi, lo;
            bsplit2(a, b, hi, lo);
            SBh[p * 72 + e] = hi;  SBl[p * 72 + e] = lo;
        }
    }
    {
        const int e = tid & 63, pg = tid >> 6;
        #pragma unroll
        for (int pp = 0; pp < 8; pp++) {
            const int p = pg * 8 + pp;
            const float a = vv[(size_t)(2 * p) * HDsz + e];
            const float b = vv[(size_t)(2 * p + 1) * HDsz + e];
            unsigned hi, lo;
            bsplit2(a, b, hi, lo);
            VBh[p * 72 + e] = hi;  VBl[p * 72 + e] = lo;
        }
    }
    if (tid < NFsz) z_s[tid] = zg[tid];
    __syncthreads();

    const int wid = tid >> 5, lane = tid & 31;
    const int wm = wid >> 2, wn = wid & 3;
    const int g  = lane >> 2, tg = lane & 3;

    float accA[2][2][4] = {};
    #pragma unroll
    for (int ks = 0; ks < 8; ks++) {
        const int k0 = ks * 8;
        unsigned a[2][4], bhf[2][2], blf[2][2];
        #pragma unroll
        for (int mt = 0; mt < 2; mt++) {
            const int mrow = wm * 32 + mt * 16 + g;
            a[mt][0] = QAh[(k0 + tg) * 72 + mrow];
            a[mt][1] = QAh[(k0 + tg) * 72 + mrow + 8];
            a[mt][2] = QAh[(k0 + tg + 4) * 72 + mrow];
            a[mt][3] = QAh[(k0 + tg + 4) * 72 + mrow + 8];
        }
        #pragma unroll
        for (int nt = 0; nt < 2; nt++) {
            const int ncol = wn * 16 + nt * 8 + g;
            bhf[nt][0] = KBh[(k0 + tg) * 72 + ncol];
            bhf[nt][1] = KBh[(k0 + tg + 4) * 72 + ncol];
            blf[nt][0] = KBl[(k0 + tg) * 72 + ncol];
            blf[nt][1] = KBl[(k0 + tg + 4) * 72 + ncol];
        }
        #pragma unroll
        for (int mt = 0; mt < 2; mt++)
            #pragma unroll
            for (int nt = 0; nt < 2; nt++) mma_bf16(accA[mt][nt], a[mt], bhf[nt]);
        #pragma unroll
        for (int mt = 0; mt < 2; mt++)
            #pragma unroll
            for (int nt = 0; nt < 2; nt++) mma_bf16(accA[mt][nt], a[mt], blf[nt]);
        #pragma unroll
        for (int mt = 0; mt < 2; mt++) {
            const int mrow = wm * 32 + mt * 16 + g;
            a[mt][0] = QAl[(k0 + tg) * 72 + mrow];
            a[mt][1] = QAl[(k0 + tg) * 72 + mrow + 8];
            a[mt][2] = QAl[(k0 + tg + 4) * 72 + mrow];
            a[mt][3] = QAl[(k0 + tg + 4) * 72 + mrow + 8];
        }
        #pragma unroll
        for (int mt = 0; mt < 2; mt++)
            #pragma unroll
            for (int nt = 0; nt < 2; nt++) mma_bf16(accA[mt][nt], a[mt], bhf[nt]);
    }
    __syncthreads();

    #pragma unroll
    for (int mt = 0; mt < 2; mt++)
        #pragma unroll
        for (int nt = 0; nt < 2; nt++)
            #pragma unroll
            for (int half = 0; half < 2; half++) {
                const int i = wm * 32 + mt * 16 + g + half * 8;
                const int j0 = wn * 16 + nt * 8 + 2 * tg;
                A_s[i * 66 + j0]     = (j0     <= i) ? accA[mt][nt][half * 2]     : 0.f;
                A_s[i * 66 + j0 + 1] = (j0 + 1 <= i) ? accA[mt][nt][half * 2 + 1] : 0.f;
            }
    __syncthreads();

    if (tid < CH) {
        const int m = tid;
        float s = EPSv;
        for (int j = 0; j < CH; j++) s += A_s[m * 66 + j];
        #pragma unroll 8
        for (int p = 0; p < 64; p++) {
            const unsigned h = QAh[p * 72 + m], l = QAl[p * 72 + m];
            const float v0 = bf_lo(h) + bf_lo(l);
            const float v1 = bf_hi(h) + bf_hi(l);
            s += v0 * z_s[2 * p] + v1 * z_s[2 * p + 1];
        }
        den_s[m] = s;
    }
    {
        const int m = tid >> 2, qt = tid & 3;
        #pragma unroll
        for (int i = 0; i < 8; i++) {
            const int p = qt * 8 + i;
            const float a0 = A_s[m * 66 + 2 * p];
            const float a1 = A_s[m * 66 + 2 * p + 1];
            unsigned hi, lo;
            bsplit2(a0, a1, hi, lo);
            Ahp[p * 72 + m] = hi;  Alp[p * 72 + m] = lo;
        }
    }
    __syncthreads();

    float accB[2][2][4] = {};
    #pragma unroll
    for (int ks = 0; ks < 4; ks++) {
        const int k0 = ks * 8;
        unsigned a[2][4], bhf[2][2], blf[2][2];
        #pragma unroll
        for (int mt = 0; mt < 2; mt++) {
            const int mrow = wm * 32 + mt * 16 + g;
            a[mt][0] = Ahp[(k0 + tg) * 72 + mrow];
            a[mt][1] = Ahp[(k0 + tg) * 72 + mrow + 8];
            a[mt][2] = Ahp[(k0 + tg + 4) * 72 + mrow];
            a[mt][3] = Ahp[(k0 + tg + 4) * 72 + mrow + 8];
        }
        #pragma unroll
        for (int nt = 0; nt < 2; nt++) {
            const int ncol = wn * 16 + nt * 8 + g;
            bhf[nt][0] = VBh[(k0 + tg) * 72 + ncol];
            bhf[nt][1] = VBh[(k0 + tg + 4) * 72 + ncol];
            blf[nt][0] = VBl[(k0 + tg) * 72 + ncol];
            blf[nt][1] = VBl[(k0 + tg + 4) * 72 + ncol];
        }
        #pragma unroll
        for (int mt = 0; mt < 2; mt++)
            #pragma unroll
            for (int nt = 0; nt < 2; nt++) mma_bf16(accB[mt][nt], a[mt], bhf[nt]);
        #pragma unroll
        for (int mt = 0; mt < 2; mt++)
            #pragma unroll
            for (int nt = 0; nt < 2; nt++) mma_bf16(accB[mt][nt], a[mt], blf[nt]);
        #pragma unroll
        for (int mt = 0; mt < 2; mt++) {
            const int mrow = wm * 32 + mt * 16 + g;
            a[mt][0] = Alp[(k0 + tg) * 72 + mrow];
            a[mt][1] = Alp[(k0 + tg) * 72 + mrow + 8];
            a[mt][2] = Alp[(k0 + tg + 4) * 72 + mrow];
            a[mt][3] = Alp[(k0 + tg + 4) * 72 + mrow + 8];
        }
        #pragma unroll
        for (int mt = 0; mt < 2; mt++)
            #pragma unroll
            for (int nt = 0; nt < 2; nt++) mma_bf16(accB[mt][nt], a[mt], bhf[nt]);
    }
    #pragma unroll
    for (int ks = 0; ks < 8; ks++) {
        const int k0 = ks * 8;
        unsigned a[2][4], bhf[2][2], blf[2][2];
        #pragma unroll
        for (int mt = 0; mt < 2; mt++) {
            const int mrow = wm * 32 + mt * 16 + g;
            a[mt][0] = QAh[(k0 + tg) * 72 + mrow];
            a[mt][1] = QAh[(k0 + tg) * 72 + mrow + 8];
            a[mt][2] = QAh[(k0 + tg + 4) * 72 + mrow];
            a[mt][3] = QAh[(k0 + tg + 4) * 72 + mrow + 8];
        }
        #pragma unroll
        for (int nt = 0; nt < 2; nt++) {
            const int ncol = wn * 16 + nt * 8 + g;
            bhf[nt][0] = SBh[(k0 + tg) * 72 + ncol];
            bhf[nt][1] = SBh[(k0 + tg + 4) * 72 + ncol];
            blf[nt][0] = SBl[(k0 + tg) * 72 + ncol];
            blf[nt][1] = SBl[(k0 + tg + 4) * 72 + ncol];
        }
        #pragma unroll
        for (int mt = 0; mt < 2; mt++)
            #pragma unroll
            for (int nt = 0; nt < 2; nt++) mma_bf16(accB[mt][nt], a[mt], bhf[nt]);
        #pragma unroll
        for (int mt = 0; mt < 2; mt++)
            #pragma unroll
            for (int nt = 0; nt < 2; nt++) mma_bf16(accB[mt][nt], a[mt], blf[nt]);
        #pragma unroll
        for (int mt = 0; mt < 2; mt++) {
            const int mrow = wm * 32 + mt * 16 + g;
            a[mt][0] = QAl[(k0 + tg) * 72 + mrow];
            a[mt][1] = QAl[(k0 + tg) * 72 + mrow + 8];
            a[mt][2] = QAl[(k0 + tg + 4) * 72 + mrow];
            a[mt][3] = QAl[(k0 + tg + 4) * 72 + mrow + 8];
        }
        #pragma unroll
        for (int mt = 0; mt < 2; mt++)
            #pragma unroll
            for (int nt = 0; nt < 2; nt++) mma_bf16(accB[mt][nt], a[mt], bhf[nt]);
    }

    const int b = bh >> 4, h = bh & 15;
    #pragma unroll
    for (int mt = 0; mt < 2; mt++)
        #pragma unroll
        for (int nt = 0; nt < 2; nt++)
            #pragma unroll
            for (int half = 0; half < 2; half++) {
                const int i = wm * 32 + mt * 16 + g + half * 8;
                const int e0 = wn * 16 + nt * 8 + 2 * tg;
                const int t = c * CH + i;
                const float inv = 1.0f / den_s[i];
                float2 val = make_float2(accB[mt][nt][half * 2] * inv,
                                         accB[mt][nt][half * 2 + 1] * inv);
                *reinterpret_cast<float2*>(
                    &g_y[((size_t)(b * Tsz + t)) * (Hn * HDsz) + h * HDsz + e0]) = val;
            }
}

// ---------------------------------------------------------------------------
extern "C" void kernel_launch(void* const* d_in, const int* in_sizes, int n_in,
                              void* d_out, int out_size)
{
    const float* x  = (const float*)d_in[0];
    const float* Wq = (const float*)d_in[1];
    const float* Wk = (const float*)d_in[2];
    const float* Wv = (const float*)d_in[3];
    const float* Wo = (const float*)d_in[4];
    const float* Wf = (const float*)d_in[5];
    float* out = (float*)d_out;

    float *q, *k, *v, *y;
    unsigned *Xh, *Xl, *Wh, *Wl;
    cudaGetSymbolAddress((void**)&q,  g_q);
    cudaGetSymbolAddress((void**)&k,  g_k);
    cudaGetSymbolAddress((void**)&v,  g_v);
    cudaGetSymbolAddress((void**)&y,  g_y);
    cudaGetSymbolAddress((void**)&Xh, g_Xh);
    cudaGetSymbolAddress((void**)&Xl, g_Xl);
    cudaGetSymbolAddress((void**)&Wh, g_Wh);
    cudaGetSymbolAddress((void**)&Wl, g_Wl);

    cudaFuncSetAttribute(bf16x2_gemm_kernel<true>,
                         cudaFuncAttributeMaxDynamicSharedMemorySize, GEMM_SMEM_BYTES);
    cudaFuncSetAttribute(bf16x2_gemm_kernel<false>,
                         cudaFuncAttributeMaxDynamicSharedMemorySize, GEMM_SMEM_BYTES);
    cudaFuncSetAttribute(featmap_mma_kernel,
                         cudaFuncAttributeMaxDynamicSharedMemorySize, FEAT_SMEM_BYTES);
    cudaFuncSetAttribute(chunk_sums_mma_kernel,
                         cudaFuncAttributeMaxDynamicSharedMemorySize, CS_SMEM_BYTES);
    cudaFuncSetAttribute(chunk_out_mma_kernel,
                         cudaFuncAttributeMaxDynamicSharedMemorySize, CO_SMEM_BYTES);

    const int WSTRIDE = KP * DM;
    pack_w_kernel<<<(KP * DM) / 256, 256>>>(Wq, Wh + 0 * WSTRIDE, Wl + 0 * WSTRIDE);
    pack_w_kernel<<<(KP * DM) / 256, 256>>>(Wk, Wh + 1 * WSTRIDE, Wl + 1 * WSTRIDE);
    pack_w_kernel<<<(KP * DM) / 256, 256>>>(Wv, Wh + 2 * WSTRIDE, Wl + 2 * WSTRIDE);
    pack_w_kernel<<<(KP * DM) / 256, 256>>>(Wo, Wh + 3 * WSTRIDE, Wl + 3 * WSTRIDE);
    pack_x_kernel<<<dim3(M_ROWS / 64, KP / 32), 256>>>(x, Xh, Xl);

    // fused QKV: grid.x = 3 weights x 8 col-blocks
    bf16x2_gemm_kernel<true><<<dim3(24, M_ROWS / 128), 256, GEMM_SMEM_BYTES>>>(
        Xh, Xl, Wh, Wl, q, k, v, M_ROWS, DM);

    featmap_mma_kernel<<<dim3(FROWS / 128, 2), 256, FEAT_SMEM_BYTES>>>(Wf);

    chunk_sums_mma_kernel<<<dim3(NCH, BHn), 256, CS_SMEM_BYTES>>>();
    prefix_kernel<<<2080, 256>>>();
    chunk_out_mma_kernel<<<dim3(NCH, BHn), 256, CO_SMEM_BYTES>>>();

    pack_x_kernel<<<dim3(M_ROWS / 64, KP / 32), 256>>>(y, Xh, Xl);
    bf16x2_gemm_kernel<false><<<dim3(8, M_ROWS / 128), 256, GEMM_SMEM_BYTES>>>(
        Xh, Xl, Wh + 3 * WSTRIDE, Wl + 3 * WSTRIDE, out, out, out, M_ROWS, DM);
}